// round 13
// baseline (speedup 1.0000x reference)
#include <cuda_runtime.h>
#include <cstdint>

// ---------------- problem constants ----------------
#define E_MAX 100000
#define T_MAX 200000
#define H 128
#define NR 16
#define NSR 112
#define NB 8

// ---------------- scratch ----------------
__device__ float g_h   [(size_t)E_MAX * H];
__device__ float g_xkj [(size_t)E_MAX * H];
__device__ float g_wt  [(size_t)9 * H * H];      // 9 transposed+rounded+k-permuted weights [n][k]
__device__ float g_bw  [(size_t)H * NB * H];     // tf32-rounded, k-permuted bil_W copy

// ---------------- helpers ----------------
__device__ __forceinline__ float tf32r(float x) {
    float y; asm("cvt.rna.tf32.f32 %0, %1;" : "=f"(y) : "f"(x)); return y;
}
__device__ __forceinline__ uint32_t cvu(float x) { return __float_as_uint(tf32r(x)); }
__device__ __forceinline__ float silu_f(float v) {
    return v * (1.0f / (1.0f + __expf(-v)));
}
__device__ __forceinline__ uint32_t smem_u32(const void* p) {
    uint32_t a;
    asm("{ .reg .u64 t; cvta.to.shared.u64 t, %1; cvt.u32.u64 %0, t; }" : "=r"(a) : "l"(p));
    return a;
}
__device__ __forceinline__ void mma_tf32(float* c, const uint32_t* a, const uint32_t* b) {
    asm volatile(
        "mma.sync.aligned.m16n8k8.row.col.f32.tf32.tf32.f32 "
        "{%0,%1,%2,%3}, {%4,%5,%6,%7}, {%8,%9}, {%0,%1,%2,%3};"
        : "+f"(c[0]), "+f"(c[1]), "+f"(c[2]), "+f"(c[3])
        : "r"(a[0]), "r"(a[1]), "r"(a[2]), "r"(a[3]), "r"(b[0]), "r"(b[1]));
}

#define BP2 136     // pitch (136 % 32 == 8) -> conflict-free LDS.64 frags
#define TILE_B2 (128 * BP2 * 4)   // 69632 bytes

// permuted slot within 8-group for logical col pair (2*t4, 2*t4+1):
// slots are (s0, s0+2)
__device__ __forceinline__ int pslot(int t4) { return (t4 < 2) ? 4 * t4 : 4 * t4 - 7; }

// ---------------- shared GEMM building blocks (512 thr, warps 4m x 4n) ----------
__device__ __forceinline__ void acc_zero(float acc[2][4][4]) {
#pragma unroll
    for (int i = 0; i < 2; i++)
#pragma unroll
        for (int j = 0; j < 4; j++)
#pragma unroll
            for (int e = 0; e < 4; e++) acc[i][j][e] = 0.f;
}

// acc += At @ Bs^T, both k-permuted (LDS.64 fragments)
__device__ __forceinline__ void mma_128p(const float* __restrict__ At,
                                         const float* __restrict__ Bs,
                                         float acc[2][4][4],
                                         int r0, int ncol, int g, int t4)
{
#pragma unroll
    for (int ks = 0; ks < 16; ks++) {
        const int k0 = ks * 8;
        uint32_t a[2][4], bb[4][2];
        float2 v00 = *(float2*)&At[(r0)      * BP2 + k0 + 2 * t4];
        float2 v01 = *(float2*)&At[(r0 + 8)  * BP2 + k0 + 2 * t4];
        float2 v10 = *(float2*)&At[(r0 + 16) * BP2 + k0 + 2 * t4];
        float2 v11 = *(float2*)&At[(r0 + 24) * BP2 + k0 + 2 * t4];
        a[0][0] = __float_as_uint(v00.x); a[0][2] = __float_as_uint(v00.y);
        a[0][1] = __float_as_uint(v01.x); a[0][3] = __float_as_uint(v01.y);
        a[1][0] = __float_as_uint(v10.x); a[1][2] = __float_as_uint(v10.y);
        a[1][1] = __float_as_uint(v11.x); a[1][3] = __float_as_uint(v11.y);
#pragma unroll
        for (int j = 0; j < 4; j++) {
            float2 w = *(float2*)&Bs[(ncol + j * 8 + g) * BP2 + k0 + 2 * t4];
            bb[j][0] = __float_as_uint(w.x);
            bb[j][1] = __float_as_uint(w.y);
        }
#pragma unroll
        for (int i = 0; i < 2; i++)
#pragma unroll
            for (int j = 0; j < 4; j++)
                mma_tf32(acc[i][j], a[i], bb[j]);
    }
}

// stage pre-permuted weight rows (linear copy)
__device__ __forceinline__ void stage_w(float* Bs, const float* __restrict__ W, int tid) {
#pragma unroll
    for (int i = 0; i < 8; i++) {
        int idx = i * 512 + tid;
        int r = idx >> 5, c4 = idx & 31;
        *(float4*)&Bs[r * BP2 + c4 * 4] = *(const float4*)&W[(size_t)r * H + c4 * 4];
    }
}
// stage global tile, tf32-rounded + k-permuted (interleave write)
__device__ __forceinline__ void stage_tile_rp(float* Tt, const float* __restrict__ A,
                                              int rowBase, int M, int tid) {
#pragma unroll
    for (int i = 0; i < 4; i++) {
        int idx = i * 512 + tid;          // 0..2047: 128 rows x 16 groups
        int r = idx >> 4, grp = idx & 15;
        int grow = rowBase + r;
        float4 lo = make_float4(0.f, 0.f, 0.f, 0.f), hi = lo;
        if (grow < M) {
            const float* src = &A[(size_t)grow * H + grp * 8];
            lo = *(const float4*)src;
            hi = *(const float4*)(src + 4);
        }
        float2* dst = (float2*)&Tt[r * BP2 + grp * 8];
        dst[0] = make_float2(tf32r(lo.x), tf32r(hi.x));
        dst[1] = make_float2(tf32r(lo.y), tf32r(hi.y));
        dst[2] = make_float2(tf32r(lo.z), tf32r(hi.z));
        dst[3] = make_float2(tf32r(lo.w), tf32r(hi.w));
    }
}
// permuted tile <- round(silu(acc + bias))
__device__ __forceinline__ void epi_to_tile_p(float* Tt, const float acc[2][4][4],
                                              const float* biasS,
                                              int mrow, int ncol, int g, int t4)
{
    const int s0 = pslot(t4);
#pragma unroll
    for (int i = 0; i < 2; i++)
#pragma unroll
        for (int half = 0; half < 2; half++) {
            int row = mrow + i * 16 + half * 8 + g;
#pragma unroll
            for (int j = 0; j < 4; j++) {
                int col = ncol + j * 8 + t4 * 2;
                int base = row * BP2 + ncol + j * 8;
                Tt[base + s0]     = tf32r(silu_f(acc[i][j][half * 2 + 0] + biasS[col]));
                Tt[base + s0 + 2] = tf32r(silu_f(acc[i][j][half * 2 + 1] + biasS[col + 1]));
            }
        }
}

// ================= fused x_ji / x_kj / rbf_h kernel ==============================
#define FJ_T0   0
#define FJ_BS   TILE_B2
#define FJ_RB   (2 * TILE_B2)
#define FJ_BIAS (3 * TILE_B2)
#define FJ_SMEM (FJ_BIAS + 1024)
#define RP 20

__global__ void __launch_bounds__(512, 1)
fused_jikj(const float* __restrict__ x, const float* __restrict__ rbf,
           const float* __restrict__ rbfW,
           const float* __restrict__ kjWt, const float* __restrict__ kjb,
           const float* __restrict__ jiWt, const float* __restrict__ jib,
           float* __restrict__ xkj_out, float* __restrict__ h_out, int M)
{
    extern __shared__ char smem[];
    float* T0 = (float*)(smem + FJ_T0);     // permuted
    float* Bs = (float*)(smem + FJ_BS);     // permuted weights
    float* RB = (float*)(smem + FJ_RB);     // logical layout (elementwise use only)
    float* bKj = (float*)(smem + FJ_BIAS);
    float* bJi = (float*)(smem + FJ_BIAS + 512);
    float* rtile = Bs;                      // [128][RP] temp before kj weight staged
    float* rw    = Bs + 128 * RP;           // [128][RP]
    const int tid = threadIdx.x;
    const int wid = tid >> 5, lane = tid & 31;
    const int g = lane >> 2, t4 = lane & 3;
    const int rowBase = blockIdx.x * 128;
    const int mrow = (wid & 3) * 32;
    const int ncol = (wid >> 2) * 32;
    const int r0 = mrow + g;

    stage_tile_rp(T0, x, rowBase, M, tid);
    // rbf A tile [128][16] (pitch RP), pre-rounded, logical layout
    {
        int r = tid >> 2, c4 = tid & 3;
        int grow = rowBase + r;
        float4 v = (grow < M) ? *(const float4*)&rbf[(size_t)grow * NR + c4 * 4]
                              : make_float4(0.f, 0.f, 0.f, 0.f);
        v.x = tf32r(v.x); v.y = tf32r(v.y); v.z = tf32r(v.z); v.w = tf32r(v.w);
        *(float4*)&rtile[r * RP + c4 * 4] = v;
    }
    // rbf_W^T pre-rounded
    {
        int n = tid >> 2, k0 = (tid & 3) * 4;
#pragma unroll
        for (int e = 0; e < 4; e++)
            rw[n * RP + k0 + e] = tf32r(rbfW[(size_t)(k0 + e) * H + n]);
    }
    if (tid < 32)       *(float4*)&bKj[tid * 4] = *(const float4*)&kjb[tid * 4];
    else if (tid < 64)  *(float4*)&bJi[(tid - 32) * 4] = *(const float4*)&jib[(tid - 32) * 4];
    __syncthreads();

    // rbf_h tile = rbf @ rbf_W  (K=16, logical LDS.32 path)
    float acc[2][4][4];
    acc_zero(acc);
#pragma unroll
    for (int ks = 0; ks < 2; ks++) {
        const int k0 = ks * 8;
        uint32_t a[2][4], bb[4][2];
        a[0][0] = __float_as_uint(rtile[(r0)      * RP + k0 + t4]);
        a[0][1] = __float_as_uint(rtile[(r0 + 8)  * RP + k0 + t4]);
        a[0][2] = __float_as_uint(rtile[(r0)      * RP + k0 + t4 + 4]);
        a[0][3] = __float_as_uint(rtile[(r0 + 8)  * RP + k0 + t4 + 4]);
        a[1][0] = __float_as_uint(rtile[(r0 + 16) * RP + k0 + t4]);
        a[1][1] = __float_as_uint(rtile[(r0 + 24) * RP + k0 + t4]);
        a[1][2] = __float_as_uint(rtile[(r0 + 16) * RP + k0 + t4 + 4]);
        a[1][3] = __float_as_uint(rtile[(r0 + 24) * RP + k0 + t4 + 4]);
#pragma unroll
        for (int j = 0; j < 4; j++) {
            int c0 = ncol + j * 8 + g;
            bb[j][0] = __float_as_uint(rw[c0 * RP + k0 + t4]);
            bb[j][1] = __float_as_uint(rw[c0 * RP + k0 + t4 + 4]);
        }
#pragma unroll
        for (int i = 0; i < 2; i++)
#pragma unroll
            for (int j = 0; j < 4; j++)
                mma_tf32(acc[i][j], a[i], bb[j]);
    }
    __syncthreads();   // done reading rtile/rw (Bs region)

    // write rbf_h to RB tile (fp32, logical layout); stage kj weight
#pragma unroll
    for (int i = 0; i < 2; i++)
#pragma unroll
        for (int half = 0; half < 2; half++) {
            int row = mrow + i * 16 + half * 8 + g;
#pragma unroll
            for (int j = 0; j < 4; j++) {
                int col = ncol + j * 8 + t4 * 2;
                *(float2*)&RB[row * BP2 + col] =
                    make_float2(acc[i][j][half * 2], acc[i][j][half * 2 + 1]);
            }
        }
    stage_w(Bs, kjWt, tid);
    __syncthreads();

    // x_kj = silu(silu(x@kjW+b)) * rbf_h
    acc_zero(acc);
    mma_128p(T0, Bs, acc, r0, ncol, g, t4);
#pragma unroll
    for (int i = 0; i < 2; i++)
#pragma unroll
        for (int half = 0; half < 2; half++) {
            int row = mrow + i * 16 + half * 8 + g;
            int grow = rowBase + row;
            if (grow >= M) continue;
#pragma unroll
            for (int j = 0; j < 4; j++) {
                int col = ncol + j * 8 + t4 * 2;
                float v0 = silu_f(silu_f(acc[i][j][half * 2 + 0] + bKj[col]));
                float v1 = silu_f(silu_f(acc[i][j][half * 2 + 1] + bKj[col + 1]));
                float2 m = *(float2*)&RB[row * BP2 + col];
                *(float2*)&xkj_out[(size_t)grow * H + col] = make_float2(v0 * m.x, v1 * m.y);
            }
        }
    __syncthreads();
    stage_w(Bs, jiWt, tid);
    __syncthreads();

    // x_ji = silu(silu(x@jiW+b))
    acc_zero(acc);
    mma_128p(T0, Bs, acc, r0, ncol, g, t4);
#pragma unroll
    for (int i = 0; i < 2; i++)
#pragma unroll
        for (int half = 0; half < 2; half++) {
            int row = mrow + i * 16 + half * 8 + g;
            int grow = rowBase + row;
            if (grow >= M) continue;
#pragma unroll
            for (int j = 0; j < 4; j++) {
                int col = ncol + j * 8 + t4 * 2;
                float v0 = silu_f(silu_f(acc[i][j][half * 2 + 0] + bJi[col]));
                float v1 = silu_f(silu_f(acc[i][j][half * 2 + 1] + bJi[col + 1]));
                *(float2*)&h_out[(size_t)grow * H + col] = make_float2(v0, v1);
            }
        }
}

// ================= fused pre-chain: 3 GEMMs ======================================
#define FP_T0   0
#define FP_T1   TILE_B2
#define FP_BS   (2 * TILE_B2)
#define FP_BIAS (3 * TILE_B2)
#define FP_SMEM (FP_BIAS + 2048)

__global__ void __launch_bounds__(512, 1)
fused_pre(const float* __restrict__ h, const float* __restrict__ x,
          const float* __restrict__ W1t, const float* __restrict__ b1,
          const float* __restrict__ W2t, const float* __restrict__ b2,
          const float* __restrict__ W3t, const float* __restrict__ b3,
          float* __restrict__ outg, int M)
{
    extern __shared__ char smem[];
    float* T0 = (float*)(smem + FP_T0);
    float* T1 = (float*)(smem + FP_T1);
    float* Bs = (float*)(smem + FP_BS);
    float* bS1 = (float*)(smem + FP_BIAS);
    float* bS2 = bS1 + 128;
    float* bS3 = bS2 + 128;
    const int tid = threadIdx.x;
    const int wid = tid >> 5, lane = tid & 31;
    const int g = lane >> 2, t4 = lane & 3;
    const int rowBase = blockIdx.x * 128;
    const int mrow = (wid & 3) * 32;
    const int ncol = (wid >> 2) * 32;
    const int r0 = mrow + g;
    const int s0 = pslot(t4);

    stage_tile_rp(T0, h, rowBase, M, tid);
    if (tid < 32)       *(float4*)&bS1[tid * 4] = *(const float4*)&b1[tid * 4];
    else if (tid < 64)  *(float4*)&bS2[(tid - 32) * 4] = *(const float4*)&b2[(tid - 32) * 4];
    else if (tid < 96)  *(float4*)&bS3[(tid - 64) * 4] = *(const float4*)&b3[(tid - 64) * 4];
    stage_w(Bs, W1t, tid);
    __syncthreads();

    float acc[2][4][4];
    acc_zero(acc);
    mma_128p(T0, Bs, acc, r0, ncol, g, t4);
    __syncthreads();
    epi_to_tile_p(T1, acc, bS1, mrow, ncol, g, t4);      // u (rounded, permuted)
    stage_w(Bs, W2t, tid);
    __syncthreads();

    acc_zero(acc);
    mma_128p(T1, Bs, acc, r0, ncol, g, t4);
    __syncthreads();
    // v = h + silu(u@W2+b2)  -> T1 (permuted slots; h from permuted T0)
#pragma unroll
    for (int i = 0; i < 2; i++)
#pragma unroll
        for (int half = 0; half < 2; half++) {
            int row = mrow + i * 16 + half * 8 + g;
#pragma unroll
            for (int j = 0; j < 4; j++) {
                int col = ncol + j * 8 + t4 * 2;
                int base = row * BP2 + ncol + j * 8;
                float r0v = T0[base + s0];
                float r1v = T0[base + s0 + 2];
                T1[base + s0]     = tf32r(r0v + silu_f(acc[i][j][half * 2 + 0] + bS2[col]));
                T1[base + s0 + 2] = tf32r(r1v + silu_f(acc[i][j][half * 2 + 1] + bS2[col + 1]));
            }
        }
    stage_w(Bs, W3t, tid);
    __syncthreads();

    acc_zero(acc);
    mma_128p(T1, Bs, acc, r0, ncol, g, t4);
    // out0 = silu(v@W3+b3) + x   (x fp32 from global)
#pragma unroll
    for (int i = 0; i < 2; i++)
#pragma unroll
        for (int half = 0; half < 2; half++) {
            int row = mrow + i * 16 + half * 8 + g;
            int grow = rowBase + row;
            if (grow >= M) continue;
#pragma unroll
            for (int j = 0; j < 4; j++) {
                int col = ncol + j * 8 + t4 * 2;
                float2 xr = *(const float2*)&x[(size_t)grow * H + col];
                float v0 = silu_f(acc[i][j][half * 2 + 0] + bS3[col]) + xr.x;
                float v1 = silu_f(acc[i][j][half * 2 + 1] + bS3[col + 1]) + xr.y;
                *(float2*)&outg[(size_t)grow * H + col] = make_float2(v0, v1);
            }
        }
}

// ================= fused post-chain: 4 GEMMs =====================================
__global__ void __launch_bounds__(512, 1)
fused_post(const float* __restrict__ h,
           const float* __restrict__ W1t, const float* __restrict__ b1,
           const float* __restrict__ W2t, const float* __restrict__ b2,
           const float* __restrict__ W3t, const float* __restrict__ b3,
           const float* __restrict__ W4t, const float* __restrict__ b4,
           float* __restrict__ outg, int M)
{
    extern __shared__ char smem[];
    float* T0 = (float*)(smem + FP_T0);
    float* T1 = (float*)(smem + FP_T1);
    float* Bs = (float*)(smem + FP_BS);
    float* bS1 = (float*)(smem + FP_BIAS);
    float* bS2 = bS1 + 128;
    float* bS3 = bS2 + 128;
    float* bS4 = bS3 + 128;
    const int tid = threadIdx.x;
    const int wid = tid >> 5, lane = tid & 31;
    const int g = lane >> 2, t4 = lane & 3;
    const int rowBase = blockIdx.x * 128;
    const int mrow = (wid & 3) * 32;
    const int ncol = (wid >> 2) * 32;
    const int r0 = mrow + g;
    const int s0 = pslot(t4);

    stage_tile_rp(T0, h, rowBase, M, tid);
    if (tid < 32)       *(float4*)&bS1[tid * 4] = *(const float4*)&b1[tid * 4];
    else if (tid < 64)  *(float4*)&bS2[(tid - 32) * 4] = *(const float4*)&b2[(tid - 32) * 4];
    else if (tid < 96)  *(float4*)&bS3[(tid - 64) * 4] = *(const float4*)&b3[(tid - 64) * 4];
    else if (tid < 128) *(float4*)&bS4[(tid - 96) * 4] = *(const float4*)&b4[(tid - 96) * 4];
    stage_w(Bs, W1t, tid);
    __syncthreads();

    float acc[2][4][4];
    acc_zero(acc);
    mma_128p(T0, Bs, acc, r0, ncol, g, t4);
    __syncthreads();
    epi_to_tile_p(T1, acc, bS1, mrow, ncol, g, t4);      // u2
    stage_w(Bs, W2t, tid);
    __syncthreads();

    acc_zero(acc);
    mma_128p(T1, Bs, acc, r0, ncol, g, t4);
    __syncthreads();
    // out1 = out0 + silu(u2@W2+b2)  -> overwrite T0 (permuted slots)
#pragma unroll
    for (int i = 0; i < 2; i++)
#pragma unroll
        for (int half = 0; half < 2; half++) {
            int row = mrow + i * 16 + half * 8 + g;
#pragma unroll
            for (int j = 0; j < 4; j++) {
                int col = ncol + j * 8 + t4 * 2;
                int base = row * BP2 + ncol + j * 8;
                float r0v = T0[base + s0];
                float r1v = T0[base + s0 + 2];
                T0[base + s0]     = tf32r(r0v + silu_f(acc[i][j][half * 2 + 0] + bS2[col]));
                T0[base + s0 + 2] = tf32r(r1v + silu_f(acc[i][j][half * 2 + 1] + bS2[col + 1]));
            }
        }
    stage_w(Bs, W3t, tid);
    __syncthreads();

    acc_zero(acc);
    mma_128p(T0, Bs, acc, r0, ncol, g, t4);
    __syncthreads();
    epi_to_tile_p(T1, acc, bS3, mrow, ncol, g, t4);      // u3
    stage_w(Bs, W4t, tid);
    __syncthreads();

    acc_zero(acc);
    mma_128p(T1, Bs, acc, r0, ncol, g, t4);
    // out = out1 + silu(u3@W4+b4)   (out1 from permuted T0)
#pragma unroll
    for (int i = 0; i < 2; i++)
#pragma unroll
        for (int half = 0; half < 2; half++) {
            int row = mrow + i * 16 + half * 8 + g;
            int grow = rowBase + row;
            if (grow >= M) continue;
#pragma unroll
            for (int j = 0; j < 4; j++) {
                int col = ncol + j * 8 + t4 * 2;
                int base = row * BP2 + ncol + j * 8;
                float r0v = T0[base + s0];
                float r1v = T0[base + s0 + 2];
                float v0 = r0v + silu_f(acc[i][j][half * 2 + 0] + bS4[col]);
                float v1 = r1v + silu_f(acc[i][j][half * 2 + 1] + bS4[col + 1]);
                *(float2*)&outg[(size_t)grow * H + col] = make_float2(v0, v1);
            }
        }
}

// ================= fused triplet (byte-identical to R12) =========================
#define TR2J   0
#define TR2K   256
#define TR2S   512
#define TR2W   2560
#define TR2RAW 6144
#define TR2B   (TR2RAW + 64 * BP2 * 4)
#define TR2_SMEM (TR2B + 128 * BP2 * 4)
#define SP 113

__device__ __forceinline__ void cpasync_bw2(uint32_t bs_u32, const float* __restrict__ bw,
                                            int b, int tid)
{
#pragma unroll
    for (int i = 0; i < 16; i++) {
        int c = i * 256 + tid;
        int r = c >> 5, c4 = c & 31;
        uint32_t dst = bs_u32 + (uint32_t)(r * BP2 + c4 * 4) * 4u;
        const float* src = bw + (size_t)r * (NB * H) + b * H + c4 * 4;
        asm volatile("cp.async.cg.shared.global [%0], [%1], 16;" :: "r"(dst), "l"(src));
    }
    asm volatile("cp.async.commit_group;" ::: "memory");
}

__global__ void __launch_bounds__(256, 2)
triplet_fused(const float* __restrict__ xkj,
              const float* __restrict__ sbf, const float* __restrict__ sbfW,
              const int* __restrict__ kj, const int* __restrict__ ji,
              const float* __restrict__ bw, float* __restrict__ hout, int T)
{
    extern __shared__ char smem[];
    int* ji_s = (int*)(smem + TR2J);
    int* ek_s = (int*)(smem + TR2K);
    float* sbf_s = (float*)(smem + TR2S);
    float* ws_s = (float*)(smem + TR2W);
    float* raw = (float*)(smem + TR2RAW);
    float* Bs = (float*)(smem + TR2B);
    float* stile = Bs;
    const int tid = threadIdx.x;
    const int wid = tid >> 5, lane = tid & 31;
    const int g = lane >> 2, t4 = lane & 3;
    const int tBase = blockIdx.x * 64;
    const int mrow = (wid & 1) * 32;
    const int ncol = (wid >> 1) * 32;
    const int r0 = mrow + g;
    const uint32_t bs_u32 = smem_u32(Bs);

    if (tid < 64) {
        int t = tBase + tid;
        ji_s[tid] = (t < T) ? ji[t] : 0;
        ek_s[tid] = (t < T) ? kj[t] : 0;
    }
    if (tid < 224) *(float4*)&ws_s[tid * 4] = *(const float4*)&sbfW[tid * 4];
#pragma unroll
    for (int i = 0; i < 7; i++) {
        int idx = i * 256 + tid;
        int r = idx / 28, c = idx % 28;
        int t = tBase + r;
        float4 v = (t < T) ? *(const float4*)&sbf[(size_t)t * NSR + c * 4]
                           : make_float4(0.f, 0.f, 0.f, 0.f);
        stile[r * SP + c * 4 + 0] = v.x;
        stile[r * SP + c * 4 + 1] = v.y;
        stile[r * SP + c * 4 + 2] = v.z;
        stile[r * SP + c * 4 + 3] = v.w;
    }
    __syncthreads();

    {
        const int r = tid >> 2, q = tid & 3;
        float a8[NB];
#pragma unroll
        for (int o = 0; o < NB; o++) a8[o] = 0.f;
        const float* myrow = &stile[r * SP + q * 28];
        const float* myw = &ws_s[q * 28 * NB];
#pragma unroll 4
        for (int k = 0; k < 28; k++) {
            float s = myrow[k];
            float4 w0 = *(const float4*)&myw[k * NB];
            float4 w1 = *(const float4*)&myw[k * NB + 4];
            a8[0] = fmaf(s, w0.x, a8[0]); a8[1] = fmaf(s, w0.y, a8[1]);
            a8[2] = fmaf(s, w0.z, a8[2]); a8[3] = fmaf(s, w0.w, a8[3]);
            a8[4] = fmaf(s, w1.x, a8[4]); a8[5] = fmaf(s, w1.y, a8[5]);
            a8[6] = fmaf(s, w1.z, a8[6]); a8[7] = fmaf(s, w1.w, a8[7]);
        }
#pragma unroll
        for (int o = 0; o < NB; o++) {
            a8[o] += __shfl_xor_sync(0xffffffffu, a8[o], 1);
            a8[o] += __shfl_xor_sync(0xffffffffu, a8[o], 2);
        }
        if (q == 0) {
            *(float4*)&sbf_s[r * NB]     = make_float4(a8[0], a8[1], a8[2], a8[3]);
            *(float4*)&sbf_s[r * NB + 4] = make_float4(a8[4], a8[5], a8[6], a8[7]);
        }
    }
#pragma unroll
    for (int i = 0; i < 4; i++) {
        int idx = i * 256 + tid;
        int r = idx >> 4, grp = idx & 15;
        int e = ek_s[r];
        const float* src = &xkj[(size_t)e * H + grp * 8];
        float4 lo = *(const float4*)src;
        float4 hi = *(const float4*)(src + 4);
        float2* dst = (float2*)&raw[r * BP2 + grp * 8];
        dst[0] = make_float2(lo.x, hi.x);
        dst[1] = make_float2(lo.y, hi.y);
        dst[2] = make_float2(lo.z, hi.z);
        dst[3] = make_float2(lo.w, hi.w);
    }

    float acc[2][4][4];
    acc_zero(acc);

    for (int b = 0; b < NB; b++) {
        __syncthreads();
        cpasync_bw2(bs_u32, bw, b, tid);
        asm volatile("cp.async.wait_group 0;" ::: "memory");
        __syncthreads();

        const float s0 = sbf_s[(r0)      * NB + b];
        const float s1 = sbf_s[(r0 + 8)  * NB + b];
        const float s2 = sbf_s[(r0 + 16) * NB + b];
        const float s3 = sbf_s[(r0 + 24) * NB + b];

#pragma unroll
        for (int ks = 0; ks < 16; ks++) {
            const int k0 = ks * 8;
            uint32_t a[2][4], bb[4][2];
            float2 v00 = *(float2*)&raw[(r0)      * BP2 + k0 + 2 * t4];
            float2 v01 = *(float2*)&raw[(r0 + 8)  * BP2 + k0 + 2 * t4];
            float2 v10 = *(float2*)&raw[(r0 + 16) * BP2 + k0 + 2 * t4];
            float2 v11 = *(float2*)&raw[(r0 + 24) * BP2 + k0 + 2 * t4];
            a[0][0] = cvu(v00.x * s0); a[0][2] = cvu(v00.y * s0);
            a[0][1] = cvu(v01.x * s1); a[0][3] = cvu(v01.y * s1);
            a[1][0] = cvu(v10.x * s2); a[1][2] = cvu(v10.y * s2);
            a[1][1] = cvu(v11.x * s3); a[1][3] = cvu(v11.y * s3);
#pragma unroll
            for (int j = 0; j < 4; j++) {
                int c0 = ncol + j * 8 + g;
                float2 w = *(float2*)&Bs[c0 * BP2 + k0 + 2 * t4];
                bb[j][0] = __float_as_uint(w.x);
                bb[j][1] = __float_as_uint(w.y);
            }
#pragma unroll
            for (int i = 0; i < 2; i++)
#pragma unroll
                for (int j = 0; j < 4; j++)
                    mma_tf32(acc[i][j], a[i], bb[j]);
        }
    }

#pragma unroll
    for (int i = 0; i < 2; i++) {
#pragma unroll
        for (int half = 0; half < 2; half++) {
            int r = mrow + i * 16 + half * 8 + g;
            int t = tBase + r;
            if (t >= T) continue;
            float* dst = &hout[(size_t)ji_s[r] * H];
#pragma unroll
            for (int j = 0; j < 4; j++) {
                int col = ncol + j * 8 + t4 * 2;
                atomicAdd(dst + col,     acc[i][j][half * 2 + 0]);
                atomicAdd(dst + col + 1, acc[i][j][half * 2 + 1]);
            }
        }
    }
}

// ================= weight prep ===================================================
struct W9 { const float* p[9]; };
// transpose + round + k-permute: out[n][perm(k)] = tf32r(in[k][n])
__global__ void transpose_w(W9 ws, float* __restrict__ out)
{
    int w = blockIdx.y;
    const float* in = ws.p[w];
    float* o = out + (size_t)w * H * H;
    int idx = blockIdx.x * 256 + threadIdx.x;
    int n = idx >> 7, k = idx & 127;
    int p = (k & ~7) + 2 * (k & 3) + ((k >> 2) & 1);
    o[n * H + p] = tf32r(in[k * H + n]);
}
// round + k-permute bil_W
__global__ void round_bilw(const float* __restrict__ in, float* __restrict__ out)
{
    int idx = blockIdx.x * 256 + threadIdx.x;
    if (idx >= H * NB * H) return;
    int k = idx & 127;
    int base = idx - k;
    int p = (k & ~7) + 2 * (k & 3) + ((k >> 2) & 1);
    out[base + p] = tf32r(in[idx]);
}

// ================= launch ========================================================
extern "C" void kernel_launch(void* const* d_in, const int* in_sizes, int n_in,
                              void* d_out, int out_size)
{
    const float* x      = (const float*)d_in[0];
    const float* rbf    = (const float*)d_in[1];
    const float* sbf    = (const float*)d_in[2];
    const int*   kj     = (const int*)  d_in[3];
    const int*   ji     = (const int*)  d_in[4];
    const float* rbf_W  = (const float*)d_in[5];
    const float* sbf_W  = (const float*)d_in[6];
    const float* ji_W   = (const float*)d_in[7];
    const float* ji_b   = (const float*)d_in[8];
    const float* kj_W   = (const float*)d_in[9];
    const float* kj_b   = (const float*)d_in[10];
    const float* bil_W  = (const float*)d_in[11];
    const float* pre_b1 = (const float*)d_in[13];
    const float* pre_b2 = (const float*)d_in[15];
    const float* pre_b3 = (const float*)d_in[17];
    const float* post_b1 = (const float*)d_in[19];
    const float* post_b2 = (const float*)d_in[21];
    const float* post_b3 = (const float*)d_in[23];
    const float* post_b4 = (const float*)d_in[25];
    float* out = (float*)d_out;

    const int E = in_sizes[0] / H;
    const int T = in_sizes[3];

    float *p_h, *p_xkj, *p_wt, *p_bw;
    cudaGetSymbolAddress((void**)&p_h,    g_h);
    cudaGetSymbolAddress((void**)&p_xkj,  g_xkj);
    cudaGetSymbolAddress((void**)&p_wt,   g_wt);
    cudaGetSymbolAddress((void**)&p_bw,   g_bw);

    cudaFuncSetAttribute(fused_jikj, cudaFuncAttributeMaxDynamicSharedMemorySize, FJ_SMEM);
    cudaFuncSetAttribute(fused_pre,  cudaFuncAttributeMaxDynamicSharedMemorySize, FP_SMEM);
    cudaFuncSetAttribute(fused_post, cudaFuncAttributeMaxDynamicSharedMemorySize, FP_SMEM);
    cudaFuncSetAttribute(triplet_fused, cudaFuncAttributeMaxDynamicSharedMemorySize, TR2_SMEM);

    const int gE = (E + 127) / 128;
    const int gT = (T + 63) / 64;

    // 0. weight prep
    W9 ws;
    ws.p[0] = ji_W; ws.p[1] = kj_W;
    ws.p[2] = (const float*)d_in[12]; ws.p[3] = (const float*)d_in[14]; ws.p[4] = (const float*)d_in[16];
    ws.p[5] = (const float*)d_in[18]; ws.p[6] = (const float*)d_in[20];
    ws.p[7] = (const float*)d_in[22]; ws.p[8] = (const float*)d_in[24];
    transpose_w<<<dim3(64, 9), 256>>>(ws, p_wt);
    round_bilw<<<(H * NB * H + 255) / 256, 256>>>(bil_W, p_bw);

    // 1. x_kj -> g_xkj, x_ji -> g_h (+ in-smem rbf_h)
    fused_jikj<<<gE, 512, FJ_SMEM>>>(x, rbf, rbf_W,
                                     p_wt + 1 * H * H, kj_b,
                                     p_wt + 0 * H * H, ji_b,
                                     p_xkj, p_h, E);
    // 2. triplet: sbf_h in-kernel + bilinear + scatter-add into g_h
    triplet_fused<<<gT, 256, TR2_SMEM>>>(p_xkj, sbf, sbf_W, kj, ji, p_bw, p_h, T);
    // 3. pre-chain (3 GEMMs fused): g_h -> g_h (in-place per CTA slice)
    fused_pre<<<gE, 512, FP_SMEM>>>(p_h, x,
                                    p_wt + 2 * H * H, pre_b1,
                                    p_wt + 3 * H * H, pre_b2,
                                    p_wt + 4 * H * H, pre_b3,
                                    p_h, E);
    // 4. post-chain (4 GEMMs fused): g_h -> out
    fused_post<<<gE, 512, FP_SMEM>>>(p_h,
                                     p_wt + 5 * H * H, post_b1,
                                     p_wt + 6 * H * H, post_b2,
                                     p_wt + 7 * H * H, post_b3,
                                     p_wt + 8 * H * H, post_b4,
                                     out, E);
}

// round 14
// speedup vs baseline: 1.0541x; 1.0541x over previous
#include <cuda_runtime.h>
#include <cstdint>

// ---------------- problem constants ----------------
#define E_MAX 100000
#define T_MAX 200000
#define H 128
#define NR 16
#define NSR 112
#define NB 8

// ---------------- scratch ----------------
__device__ float g_h   [(size_t)E_MAX * H];
__device__ float g_xkj [(size_t)E_MAX * H];
__device__ float g_wt  [(size_t)9 * H * H];      // 9 transposed+rounded weights [n][k]
__device__ float g_bw  [(size_t)H * NB * H];     // tf32-rounded, k-permuted bil_W copy

// ---------------- helpers ----------------
__device__ __forceinline__ float tf32r(float x) {
    float y; asm("cvt.rna.tf32.f32 %0, %1;" : "=f"(y) : "f"(x)); return y;
}
__device__ __forceinline__ float silu_f(float v) {
    return v * (1.0f / (1.0f + __expf(-v)));
}
__device__ __forceinline__ uint32_t smem_u32(const void* p) {
    uint32_t a;
    asm("{ .reg .u64 t; cvta.to.shared.u64 t, %1; cvt.u32.u64 %0, t; }" : "=r"(a) : "l"(p));
    return a;
}
__device__ __forceinline__ void mma_tf32(float* c, const uint32_t* a, const uint32_t* b) {
    asm volatile(
        "mma.sync.aligned.m16n8k8.row.col.f32.tf32.tf32.f32 "
        "{%0,%1,%2,%3}, {%4,%5,%6,%7}, {%8,%9}, {%0,%1,%2,%3};"
        : "+f"(c[0]), "+f"(c[1]), "+f"(c[2]), "+f"(c[3])
        : "r"(a[0]), "r"(a[1]), "r"(a[2]), "r"(a[3]), "r"(b[0]), "r"(b[1]));
}

#define BP 132      // chain-kernel pitch (132 % 32 == 4, conflict-free LDS.32 frags)
#define BP2 136     // triplet pitch (136 % 32 == 8, conflict-free LDS.64 frags)
#define TILE_B (128 * BP * 4)   // 67584 bytes

// ---------------- shared GEMM building blocks (512 thr, warps 4m x 4n) ----------
__device__ __forceinline__ void acc_zero(float acc[2][4][4]) {
#pragma unroll
    for (int i = 0; i < 2; i++)
#pragma unroll
        for (int j = 0; j < 4; j++)
#pragma unroll
            for (int e = 0; e < 4; e++) acc[i][j][e] = 0.f;
}

__device__ __forceinline__ void mma_128(const float* __restrict__ At,
                                        const float* __restrict__ Bs,
                                        float acc[2][4][4],
                                        int r0, int ncol, int g, int t4)
{
#pragma unroll
    for (int ks = 0; ks < 16; ks++) {
        const int k0 = ks * 8;
        uint32_t a[2][4], bb[4][2];
        a[0][0] = __float_as_uint(At[(r0)      * BP + k0 + t4]);
        a[0][1] = __float_as_uint(At[(r0 + 8)  * BP + k0 + t4]);
        a[0][2] = __float_as_uint(At[(r0)      * BP + k0 + t4 + 4]);
        a[0][3] = __float_as_uint(At[(r0 + 8)  * BP + k0 + t4 + 4]);
        a[1][0] = __float_as_uint(At[(r0 + 16) * BP + k0 + t4]);
        a[1][1] = __float_as_uint(At[(r0 + 24) * BP + k0 + t4]);
        a[1][2] = __float_as_uint(At[(r0 + 16) * BP + k0 + t4 + 4]);
        a[1][3] = __float_as_uint(At[(r0 + 24) * BP + k0 + t4 + 4]);
#pragma unroll
        for (int j = 0; j < 4; j++) {
            int c0 = ncol + j * 8 + g;
            bb[j][0] = __float_as_uint(Bs[c0 * BP + k0 + t4]);
            bb[j][1] = __float_as_uint(Bs[c0 * BP + k0 + t4 + 4]);
        }
#pragma unroll
        for (int i = 0; i < 2; i++)
#pragma unroll
            for (int j = 0; j < 4; j++)
                mma_tf32(acc[i][j], a[i], bb[j]);
    }
}

__device__ __forceinline__ void stage_w(float* Bs, const float* __restrict__ W, int tid) {
#pragma unroll
    for (int i = 0; i < 8; i++) {
        int idx = i * 512 + tid;
        int r = idx >> 5, c4 = idx & 31;
        *(float4*)&Bs[r * BP + c4 * 4] = *(const float4*)&W[(size_t)r * H + c4 * 4];
    }
}
__device__ __forceinline__ void stage_tile_r(float* Tt, const float* __restrict__ A,
                                             int rowBase, int M, int tid) {
#pragma unroll
    for (int i = 0; i < 8; i++) {
        int idx = i * 512 + tid;
        int r = idx >> 5, c4 = idx & 31;
        int grow = rowBase + r;
        float4 v = (grow < M) ? *(const float4*)&A[(size_t)grow * H + c4 * 4]
                              : make_float4(0.f, 0.f, 0.f, 0.f);
        v.x = tf32r(v.x); v.y = tf32r(v.y); v.z = tf32r(v.z); v.w = tf32r(v.w);
        *(float4*)&Tt[r * BP + c4 * 4] = v;
    }
}
__device__ __forceinline__ void epi_to_tile(float* Tt, const float acc[2][4][4],
                                            const float* biasS,
                                            int mrow, int ncol, int g, int t4)
{
#pragma unroll
    for (int i = 0; i < 2; i++)
#pragma unroll
        for (int half = 0; half < 2; half++) {
            int row = mrow + i * 16 + half * 8 + g;
#pragma unroll
            for (int j = 0; j < 4; j++) {
                int col = ncol + j * 8 + t4 * 2;
                float v0 = tf32r(silu_f(acc[i][j][half * 2 + 0] + biasS[col]));
                float v1 = tf32r(silu_f(acc[i][j][half * 2 + 1] + biasS[col + 1]));
                *(float2*)&Tt[row * BP + col] = make_float2(v0, v1);
            }
        }
}

// ================= fused x_ji / x_kj / rbf_h kernel ==============================
#define FJ_T0   0
#define FJ_BS   TILE_B
#define FJ_RB   (2 * TILE_B)
#define FJ_BIAS (3 * TILE_B)
#define FJ_SMEM (FJ_BIAS + 1024)
#define RP 20

__global__ void __launch_bounds__(512, 1)
fused_jikj(const float* __restrict__ x, const float* __restrict__ rbf,
           const float* __restrict__ rbfW,
           const float* __restrict__ kjWt, const float* __restrict__ kjb,
           const float* __restrict__ jiWt, const float* __restrict__ jib,
           float* __restrict__ xkj_out, float* __restrict__ h_out, int M)
{
    extern __shared__ char smem[];
    float* T0 = (float*)(smem + FJ_T0);
    float* Bs = (float*)(smem + FJ_BS);
    float* RB = (float*)(smem + FJ_RB);
    float* bKj = (float*)(smem + FJ_BIAS);
    float* bJi = (float*)(smem + FJ_BIAS + 512);
    float* rtile = Bs;
    float* rw    = Bs + 128 * RP;
    const int tid = threadIdx.x;
    const int wid = tid >> 5, lane = tid & 31;
    const int g = lane >> 2, t4 = lane & 3;
    const int rowBase = blockIdx.x * 128;
    const int mrow = (wid & 3) * 32;
    const int ncol = (wid >> 2) * 32;
    const int r0 = mrow + g;

    stage_tile_r(T0, x, rowBase, M, tid);
    {
        int r = tid >> 2, c4 = tid & 3;
        int grow = rowBase + r;
        float4 v = (grow < M) ? *(const float4*)&rbf[(size_t)grow * NR + c4 * 4]
                              : make_float4(0.f, 0.f, 0.f, 0.f);
        v.x = tf32r(v.x); v.y = tf32r(v.y); v.z = tf32r(v.z); v.w = tf32r(v.w);
        *(float4*)&rtile[r * RP + c4 * 4] = v;
    }
    {
        int n = tid >> 2, k0 = (tid & 3) * 4;
#pragma unroll
        for (int e = 0; e < 4; e++)
            rw[n * RP + k0 + e] = tf32r(rbfW[(size_t)(k0 + e) * H + n]);
    }
    if (tid < 32)       *(float4*)&bKj[tid * 4] = *(const float4*)&kjb[tid * 4];
    else if (tid < 64)  *(float4*)&bJi[(tid - 32) * 4] = *(const float4*)&jib[(tid - 32) * 4];
    __syncthreads();

    float acc[2][4][4];
    acc_zero(acc);
#pragma unroll
    for (int ks = 0; ks < 2; ks++) {
        const int k0 = ks * 8;
        uint32_t a[2][4], bb[4][2];
        a[0][0] = __float_as_uint(rtile[(r0)      * RP + k0 + t4]);
        a[0][1] = __float_as_uint(rtile[(r0 + 8)  * RP + k0 + t4]);
        a[0][2] = __float_as_uint(rtile[(r0)      * RP + k0 + t4 + 4]);
        a[0][3] = __float_as_uint(rtile[(r0 + 8)  * RP + k0 + t4 + 4]);
        a[1][0] = __float_as_uint(rtile[(r0 + 16) * RP + k0 + t4]);
        a[1][1] = __float_as_uint(rtile[(r0 + 24) * RP + k0 + t4]);
        a[1][2] = __float_as_uint(rtile[(r0 + 16) * RP + k0 + t4 + 4]);
        a[1][3] = __float_as_uint(rtile[(r0 + 24) * RP + k0 + t4 + 4]);
#pragma unroll
        for (int j = 0; j < 4; j++) {
            int c0 = ncol + j * 8 + g;
            bb[j][0] = __float_as_uint(rw[c0 * RP + k0 + t4]);
            bb[j][1] = __float_as_uint(rw[c0 * RP + k0 + t4 + 4]);
        }
#pragma unroll
        for (int i = 0; i < 2; i++)
#pragma unroll
            for (int j = 0; j < 4; j++)
                mma_tf32(acc[i][j], a[i], bb[j]);
    }
    __syncthreads();

#pragma unroll
    for (int i = 0; i < 2; i++)
#pragma unroll
        for (int half = 0; half < 2; half++) {
            int row = mrow + i * 16 + half * 8 + g;
#pragma unroll
            for (int j = 0; j < 4; j++) {
                int col = ncol + j * 8 + t4 * 2;
                *(float2*)&RB[row * BP + col] =
                    make_float2(acc[i][j][half * 2], acc[i][j][half * 2 + 1]);
            }
        }
    stage_w(Bs, kjWt, tid);
    __syncthreads();

    acc_zero(acc);
    mma_128(T0, Bs, acc, r0, ncol, g, t4);
#pragma unroll
    for (int i = 0; i < 2; i++)
#pragma unroll
        for (int half = 0; half < 2; half++) {
            int row = mrow + i * 16 + half * 8 + g;
            int grow = rowBase + row;
            if (grow >= M) continue;
#pragma unroll
            for (int j = 0; j < 4; j++) {
                int col = ncol + j * 8 + t4 * 2;
                float v0 = silu_f(silu_f(acc[i][j][half * 2 + 0] + bKj[col]));
                float v1 = silu_f(silu_f(acc[i][j][half * 2 + 1] + bKj[col + 1]));
                float2 m = *(float2*)&RB[row * BP + col];
                *(float2*)&xkj_out[(size_t)grow * H + col] = make_float2(v0 * m.x, v1 * m.y);
            }
        }
    __syncthreads();
    stage_w(Bs, jiWt, tid);
    __syncthreads();

    acc_zero(acc);
    mma_128(T0, Bs, acc, r0, ncol, g, t4);
#pragma unroll
    for (int i = 0; i < 2; i++)
#pragma unroll
        for (int half = 0; half < 2; half++) {
            int row = mrow + i * 16 + half * 8 + g;
            int grow = rowBase + row;
            if (grow >= M) continue;
#pragma unroll
            for (int j = 0; j < 4; j++) {
                int col = ncol + j * 8 + t4 * 2;
                float v0 = silu_f(silu_f(acc[i][j][half * 2 + 0] + bJi[col]));
                float v1 = silu_f(silu_f(acc[i][j][half * 2 + 1] + bJi[col + 1]));
                *(float2*)&h_out[(size_t)grow * H + col] = make_float2(v0, v1);
            }
        }
}

// ================= fused pre-chain: 3 GEMMs ======================================
#define FP_T0   0
#define FP_T1   TILE_B
#define FP_BS   (2 * TILE_B)
#define FP_BIAS (3 * TILE_B)
#define FP_SMEM (FP_BIAS + 2048)

__global__ void __launch_bounds__(512, 1)
fused_pre(const float* __restrict__ h, const float* __restrict__ x,
          const float* __restrict__ W1t, const float* __restrict__ b1,
          const float* __restrict__ W2t, const float* __restrict__ b2,
          const float* __restrict__ W3t, const float* __restrict__ b3,
          float* __restrict__ outg, int M)
{
    extern __shared__ char smem[];
    float* T0 = (float*)(smem + FP_T0);
    float* T1 = (float*)(smem + FP_T1);
    float* Bs = (float*)(smem + FP_BS);
    float* bS1 = (float*)(smem + FP_BIAS);
    float* bS2 = bS1 + 128;
    float* bS3 = bS2 + 128;
    const int tid = threadIdx.x;
    const int wid = tid >> 5, lane = tid & 31;
    const int g = lane >> 2, t4 = lane & 3;
    const int rowBase = blockIdx.x * 128;
    const int mrow = (wid & 3) * 32;
    const int ncol = (wid >> 2) * 32;
    const int r0 = mrow + g;

    stage_tile_r(T0, h, rowBase, M, tid);
    if (tid < 32)       *(float4*)&bS1[tid * 4] = *(const float4*)&b1[tid * 4];
    else if (tid < 64)  *(float4*)&bS2[(tid - 32) * 4] = *(const float4*)&b2[(tid - 32) * 4];
    else if (tid < 96)  *(float4*)&bS3[(tid - 64) * 4] = *(const float4*)&b3[(tid - 64) * 4];
    stage_w(Bs, W1t, tid);
    __syncthreads();

    float acc[2][4][4];
    acc_zero(acc);
    mma_128(T0, Bs, acc, r0, ncol, g, t4);
    __syncthreads();
    epi_to_tile(T1, acc, bS1, mrow, ncol, g, t4);
    stage_w(Bs, W2t, tid);
    __syncthreads();

    acc_zero(acc);
    mma_128(T1, Bs, acc, r0, ncol, g, t4);
    __syncthreads();
#pragma unroll
    for (int i = 0; i < 2; i++)
#pragma unroll
        for (int half = 0; half < 2; half++) {
            int row = mrow + i * 16 + half * 8 + g;
#pragma unroll
            for (int j = 0; j < 4; j++) {
                int col = ncol + j * 8 + t4 * 2;
                float2 res = *(float2*)&T0[row * BP + col];
                float v0 = tf32r(res.x + silu_f(acc[i][j][half * 2 + 0] + bS2[col]));
                float v1 = tf32r(res.y + silu_f(acc[i][j][half * 2 + 1] + bS2[col + 1]));
                *(float2*)&T1[row * BP + col] = make_float2(v0, v1);
            }
        }
    stage_w(Bs, W3t, tid);
    __syncthreads();

    acc_zero(acc);
    mma_128(T1, Bs, acc, r0, ncol, g, t4);
#pragma unroll
    for (int i = 0; i < 2; i++)
#pragma unroll
        for (int half = 0; half < 2; half++) {
            int row = mrow + i * 16 + half * 8 + g;
            int grow = rowBase + row;
            if (grow >= M) continue;
#pragma unroll
            for (int j = 0; j < 4; j++) {
                int col = ncol + j * 8 + t4 * 2;
                float2 xr = *(const float2*)&x[(size_t)grow * H + col];
                float v0 = silu_f(acc[i][j][half * 2 + 0] + bS3[col]) + xr.x;
                float v1 = silu_f(acc[i][j][half * 2 + 1] + bS3[col + 1]) + xr.y;
                *(float2*)&outg[(size_t)grow * H + col] = make_float2(v0, v1);
            }
        }
}

// ================= fused post-chain: 4 GEMMs =====================================
__global__ void __launch_bounds__(512, 1)
fused_post(const float* __restrict__ h,
           const float* __restrict__ W1t, const float* __restrict__ b1,
           const float* __restrict__ W2t, const float* __restrict__ b2,
           const float* __restrict__ W3t, const float* __restrict__ b3,
           const float* __restrict__ W4t, const float* __restrict__ b4,
           float* __restrict__ outg, int M)
{
    extern __shared__ char smem[];
    float* T0 = (float*)(smem + FP_T0);
    float* T1 = (float*)(smem + FP_T1);
    float* Bs = (float*)(smem + FP_BS);
    float* bS1 = (float*)(smem + FP_BIAS);
    float* bS2 = bS1 + 128;
    float* bS3 = bS2 + 128;
    float* bS4 = bS3 + 128;
    const int tid = threadIdx.x;
    const int wid = tid >> 5, lane = tid & 31;
    const int g = lane >> 2, t4 = lane & 3;
    const int rowBase = blockIdx.x * 128;
    const int mrow = (wid & 3) * 32;
    const int ncol = (wid >> 2) * 32;
    const int r0 = mrow + g;

    stage_tile_r(T0, h, rowBase, M, tid);
    if (tid < 32)       *(float4*)&bS1[tid * 4] = *(const float4*)&b1[tid * 4];
    else if (tid < 64)  *(float4*)&bS2[(tid - 32) * 4] = *(const float4*)&b2[(tid - 32) * 4];
    else if (tid < 96)  *(float4*)&bS3[(tid - 64) * 4] = *(const float4*)&b3[(tid - 64) * 4];
    else if (tid < 128) *(float4*)&bS4[(tid - 96) * 4] = *(const float4*)&b4[(tid - 96) * 4];
    stage_w(Bs, W1t, tid);
    __syncthreads();

    float acc[2][4][4];
    acc_zero(acc);
    mma_128(T0, Bs, acc, r0, ncol, g, t4);
    __syncthreads();
    epi_to_tile(T1, acc, bS1, mrow, ncol, g, t4);
    stage_w(Bs, W2t, tid);
    __syncthreads();

    acc_zero(acc);
    mma_128(T1, Bs, acc, r0, ncol, g, t4);
    __syncthreads();
#pragma unroll
    for (int i = 0; i < 2; i++)
#pragma unroll
        for (int half = 0; half < 2; half++) {
            int row = mrow + i * 16 + half * 8 + g;
#pragma unroll
            for (int j = 0; j < 4; j++) {
                int col = ncol + j * 8 + t4 * 2;
                float2 res = *(float2*)&T0[row * BP + col];
                float v0 = tf32r(res.x + silu_f(acc[i][j][half * 2 + 0] + bS2[col]));
                float v1 = tf32r(res.y + silu_f(acc[i][j][half * 2 + 1] + bS2[col + 1]));
                *(float2*)&T0[row * BP + col] = make_float2(v0, v1);
            }
        }
    stage_w(Bs, W3t, tid);
    __syncthreads();

    acc_zero(acc);
    mma_128(T0, Bs, acc, r0, ncol, g, t4);
    __syncthreads();
    epi_to_tile(T1, acc, bS3, mrow, ncol, g, t4);
    stage_w(Bs, W4t, tid);
    __syncthreads();

    acc_zero(acc);
    mma_128(T1, Bs, acc, r0, ncol, g, t4);
#pragma unroll
    for (int i = 0; i < 2; i++)
#pragma unroll
        for (int half = 0; half < 2; half++) {
            int row = mrow + i * 16 + half * 8 + g;
            int grow = rowBase + row;
            if (grow >= M) continue;
#pragma unroll
            for (int j = 0; j < 4; j++) {
                int col = ncol + j * 8 + t4 * 2;
                float2 res = *(float2*)&T0[row * BP + col];
                float v0 = res.x + silu_f(acc[i][j][half * 2 + 0] + bS4[col]);
                float v1 = res.y + silu_f(acc[i][j][half * 2 + 1] + bS4[col + 1]);
                *(float2*)&outg[(size_t)grow * H + col] = make_float2(v0, v1);
            }
        }
}

// ================= fused triplet: k-permuted LDS.64, A fed as raw fp32 ===========
// 64 triplets x 128 cols, 256 threads, 8 warps (2m x 4n), warp tile 32x32.
#define TR2J   0
#define TR2K   256
#define TR2S   512
#define TR2W   2560
#define TR2RAW 6144
#define TR2B   (TR2RAW + 64 * BP2 * 4)
#define TR2_SMEM (TR2B + 128 * BP2 * 4)
#define SP 113

__device__ __forceinline__ void cpasync_bw2(uint32_t bs_u32, const float* __restrict__ bw,
                                            int b, int tid)
{
#pragma unroll
    for (int i = 0; i < 16; i++) {
        int c = i * 256 + tid;
        int r = c >> 5, c4 = c & 31;
        uint32_t dst = bs_u32 + (uint32_t)(r * BP2 + c4 * 4) * 4u;
        const float* src = bw + (size_t)r * (NB * H) + b * H + c4 * 4;
        asm volatile("cp.async.cg.shared.global [%0], [%1], 16;" :: "r"(dst), "l"(src));
    }
    asm volatile("cp.async.commit_group;" ::: "memory");
}

__global__ void __launch_bounds__(256, 2)
triplet_fused(const float* __restrict__ xkj,
              const float* __restrict__ sbf, const float* __restrict__ sbfW,
              const int* __restrict__ kj, const int* __restrict__ ji,
              const float* __restrict__ bw, float* __restrict__ hout, int T)
{
    extern __shared__ char smem[];
    int* ji_s = (int*)(smem + TR2J);
    int* ek_s = (int*)(smem + TR2K);
    float* sbf_s = (float*)(smem + TR2S);
    float* ws_s = (float*)(smem + TR2W);
    float* raw = (float*)(smem + TR2RAW);
    float* Bs = (float*)(smem + TR2B);
    float* stile = Bs;
    const int tid = threadIdx.x;
    const int wid = tid >> 5, lane = tid & 31;
    const int g = lane >> 2, t4 = lane & 3;
    const int tBase = blockIdx.x * 64;
    const int mrow = (wid & 1) * 32;
    const int ncol = (wid >> 1) * 32;
    const int r0 = mrow + g;
    const uint32_t bs_u32 = smem_u32(Bs);

    if (tid < 64) {
        int t = tBase + tid;
        ji_s[tid] = (t < T) ? ji[t] : 0;
        ek_s[tid] = (t < T) ? kj[t] : 0;
    }
    if (tid < 224) *(float4*)&ws_s[tid * 4] = *(const float4*)&sbfW[tid * 4];
#pragma unroll
    for (int i = 0; i < 7; i++) {
        int idx = i * 256 + tid;
        int r = idx / 28, c = idx % 28;
        int t = tBase + r;
        float4 v = (t < T) ? *(const float4*)&sbf[(size_t)t * NSR + c * 4]
                           : make_float4(0.f, 0.f, 0.f, 0.f);
        stile[r * SP + c * 4 + 0] = v.x;
        stile[r * SP + c * 4 + 1] = v.y;
        stile[r * SP + c * 4 + 2] = v.z;
        stile[r * SP + c * 4 + 3] = v.w;
    }
    __syncthreads();

    // sbf_h: 4 threads per row, 28 k's each, shfl-reduce
    {
        const int r = tid >> 2, q = tid & 3;
        float a8[NB];
#pragma unroll
        for (int o = 0; o < NB; o++) a8[o] = 0.f;
        const float* myrow = &stile[r * SP + q * 28];
        const float* myw = &ws_s[q * 28 * NB];
#pragma unroll 4
        for (int k = 0; k < 28; k++) {
            float s = myrow[k];
            float4 w0 = *(const float4*)&myw[k * NB];
            float4 w1 = *(const float4*)&myw[k * NB + 4];
            a8[0] = fmaf(s, w0.x, a8[0]); a8[1] = fmaf(s, w0.y, a8[1]);
            a8[2] = fmaf(s, w0.z, a8[2]); a8[3] = fmaf(s, w0.w, a8[3]);
            a8[4] = fmaf(s, w1.x, a8[4]); a8[5] = fmaf(s, w1.y, a8[5]);
            a8[6] = fmaf(s, w1.z, a8[6]); a8[7] = fmaf(s, w1.w, a8[7]);
        }
#pragma unroll
        for (int o = 0; o < NB; o++) {
            a8[o] += __shfl_xor_sync(0xffffffffu, a8[o], 1);
            a8[o] += __shfl_xor_sync(0xffffffffu, a8[o], 2);
        }
        if (q == 0) {
            *(float4*)&sbf_s[r * NB]     = make_float4(a8[0], a8[1], a8[2], a8[3]);
            *(float4*)&sbf_s[r * NB + 4] = make_float4(a8[4], a8[5], a8[6], a8[7]);
        }
    }
    // gather x_kj rows into raw, k-permuted interleave
#pragma unroll
    for (int i = 0; i < 4; i++) {
        int idx = i * 256 + tid;
        int r = idx >> 4, grp = idx & 15;
        int e = ek_s[r];
        const float* src = &xkj[(size_t)e * H + grp * 8];
        float4 lo = *(const float4*)src;
        float4 hi = *(const float4*)(src + 4);
        float2* dst = (float2*)&raw[r * BP2 + grp * 8];
        dst[0] = make_float2(lo.x, hi.x);
        dst[1] = make_float2(lo.y, hi.y);
        dst[2] = make_float2(lo.z, hi.z);
        dst[3] = make_float2(lo.w, hi.w);
    }

    float acc[2][4][4];
    acc_zero(acc);

    for (int b = 0; b < NB; b++) {
        __syncthreads();
        cpasync_bw2(bs_u32, bw, b, tid);
        asm volatile("cp.async.wait_group 0;" ::: "memory");
        __syncthreads();

        const float s0 = sbf_s[(r0)      * NB + b];
        const float s1 = sbf_s[(r0 + 8)  * NB + b];
        const float s2 = sbf_s[(r0 + 16) * NB + b];
        const float s3 = sbf_s[(r0 + 24) * NB + b];

#pragma unroll
        for (int ks = 0; ks < 16; ks++) {
            const int k0 = ks * 8;
            uint32_t a[2][4], bb[4][2];
            float2 v00 = *(float2*)&raw[(r0)      * BP2 + k0 + 2 * t4];
            float2 v01 = *(float2*)&raw[(r0 + 8)  * BP2 + k0 + 2 * t4];
            float2 v10 = *(float2*)&raw[(r0 + 16) * BP2 + k0 + 2 * t4];
            float2 v11 = *(float2*)&raw[(r0 + 24) * BP2 + k0 + 2 * t4];
            // feed raw fp32 product directly; HW truncates to tf32 (no CVT)
            a[0][0] = __float_as_uint(v00.x * s0); a[0][2] = __float_as_uint(v00.y * s0);
            a[0][1] = __float_as_uint(v01.x * s1); a[0][3] = __float_as_uint(v01.y * s1);
            a[1][0] = __float_as_uint(v10.x * s2); a[1][2] = __float_as_uint(v10.y * s2);
            a[1][1] = __float_as_uint(v11.x * s3); a[1][3] = __float_as_uint(v11.y * s3);
#pragma unroll
            for (int j = 0; j < 4; j++) {
                int c0 = ncol + j * 8 + g;
                float2 w = *(float2*)&Bs[c0 * BP2 + k0 + 2 * t4];
                bb[j][0] = __float_as_uint(w.x);
                bb[j][1] = __float_as_uint(w.y);
            }
#pragma unroll
            for (int i = 0; i < 2; i++)
#pragma unroll
                for (int j = 0; j < 4; j++)
                    mma_tf32(acc[i][j], a[i], bb[j]);
        }
    }

#pragma unroll
    for (int i = 0; i < 2; i++) {
#pragma unroll
        for (int half = 0; half < 2; half++) {
            int r = mrow + i * 16 + half * 8 + g;
            int t = tBase + r;
            if (t >= T) continue;
            float* dst = &hout[(size_t)ji_s[r] * H];
#pragma unroll
            for (int j = 0; j < 4; j++) {
                int col = ncol + j * 8 + t4 * 2;
                atomicAdd(dst + col,     acc[i][j][half * 2 + 0]);
                atomicAdd(dst + col + 1, acc[i][j][half * 2 + 1]);
            }
        }
    }
}

// ================= weight prep ===================================================
struct W9 { const float* p[9]; };
// transpose + round (logical layout for chain kernels)
__global__ void transpose_w(W9 ws, float* __restrict__ out)
{
    int w = blockIdx.y;
    const float* in = ws.p[w];
    float* o = out + (size_t)w * H * H;
    int idx = blockIdx.x * 256 + threadIdx.x;
    int n = idx >> 7, k = idx & 127;
    o[n * H + k] = tf32r(in[k * H + n]);
}
// round + k-permute bil_W (triplet layout)
__global__ void round_bilw(const float* __restrict__ in, float* __restrict__ out)
{
    int idx = blockIdx.x * 256 + threadIdx.x;
    if (idx >= H * NB * H) return;
    int k = idx & 127;
    int base = idx - k;
    int p = (k & ~7) + 2 * (k & 3) + ((k >> 2) & 1);
    out[base + p] = tf32r(in[idx]);
}

// ================= launch ========================================================
extern "C" void kernel_launch(void* const* d_in, const int* in_sizes, int n_in,
                              void* d_out, int out_size)
{
    const float* x      = (const float*)d_in[0];
    const float* rbf    = (const float*)d_in[1];
    const float* sbf    = (const float*)d_in[2];
    const int*   kj     = (const int*)  d_in[3];
    const int*   ji     = (const int*)  d_in[4];
    const float* rbf_W  = (const float*)d_in[5];
    const float* sbf_W  = (const float*)d_in[6];
    const float* ji_W   = (const float*)d_in[7];
    const float* ji_b   = (const float*)d_in[8];
    const float* kj_W   = (const float*)d_in[9];
    const float* kj_b   = (const float*)d_in[10];
    const float* bil_W  = (const float*)d_in[11];
    const float* pre_b1 = (const float*)d_in[13];
    const float* pre_b2 = (const float*)d_in[15];
    const float* pre_b3 = (const float*)d_in[17];
    const float* post_b1 = (const float*)d_in[19];
    const float* post_b2 = (const float*)d_in[21];
    const float* post_b3 = (const float*)d_in[23];
    const float* post_b4 = (const float*)d_in[25];
    float* out = (float*)d_out;

    const int E = in_sizes[0] / H;
    const int T = in_sizes[3];

    float *p_h, *p_xkj, *p_wt, *p_bw;
    cudaGetSymbolAddress((void**)&p_h,    g_h);
    cudaGetSymbolAddress((void**)&p_xkj,  g_xkj);
    cudaGetSymbolAddress((void**)&p_wt,   g_wt);
    cudaGetSymbolAddress((void**)&p_bw,   g_bw);

    cudaFuncSetAttribute(fused_jikj, cudaFuncAttributeMaxDynamicSharedMemorySize, FJ_SMEM);
    cudaFuncSetAttribute(fused_pre,  cudaFuncAttributeMaxDynamicSharedMemorySize, FP_SMEM);
    cudaFuncSetAttribute(fused_post, cudaFuncAttributeMaxDynamicSharedMemorySize, FP_SMEM);
    cudaFuncSetAttribute(triplet_fused, cudaFuncAttributeMaxDynamicSharedMemorySize, TR2_SMEM);

    const int gE = (E + 127) / 128;
    const int gT = (T + 63) / 64;

    // 0. weight prep
    W9 ws;
    ws.p[0] = ji_W; ws.p[1] = kj_W;
    ws.p[2] = (const float*)d_in[12]; ws.p[3] = (const float*)d_in[14]; ws.p[4] = (const float*)d_in[16];
    ws.p[5] = (const float*)d_in[18]; ws.p[6] = (const float*)d_in[20];
    ws.p[7] = (const float*)d_in[22]; ws.p[8] = (const float*)d_in[24];
    transpose_w<<<dim3(64, 9), 256>>>(ws, p_wt);
    round_bilw<<<(H * NB * H + 255) / 256, 256>>>(bil_W, p_bw);

    // 1. x_kj -> g_xkj, x_ji -> g_h (+ in-smem rbf_h)
    fused_jikj<<<gE, 512, FJ_SMEM>>>(x, rbf, rbf_W,
                                     p_wt + 1 * H * H, kj_b,
                                     p_wt + 0 * H * H, ji_b,
                                     p_xkj, p_h, E);
    // 2. triplet: sbf_h in-kernel + bilinear + scatter-add into g_h
    triplet_fused<<<gT, 256, TR2_SMEM>>>(p_xkj, sbf, sbf_W, kj, ji, p_bw, p_h, T);
    // 3. pre-chain (3 GEMMs fused): g_h -> g_h (in-place per CTA slice)
    fused_pre<<<gE, 512, FP_SMEM>>>(p_h, x,
                                    p_wt + 2 * H * H, pre_b1,
                                    p_wt + 3 * H * H, pre_b2,
                                    p_wt + 4 * H * H, pre_b3,
                                    p_h, E);
    // 4. post-chain (4 GEMMs fused): g_h -> out
    fused_post<<<gE, 512, FP_SMEM>>>(p_h,
                                     p_wt + 5 * H * H, post_b1,
                                     p_wt + 6 * H * H, post_b2,
                                     p_wt + 7 * H * H, post_b3,
                                     p_wt + 8 * H * H, post_b4,
                                     out, E);
}

// round 16
// speedup vs baseline: 1.0824x; 1.0269x over previous
#include <cuda_runtime.h>
#include <cstdint>

// ---------------- problem constants ----------------
#define E_MAX 100000
#define T_MAX 200000
#define H 128
#define NR 16
#define NSR 112
#define NB 8

// ---------------- scratch ----------------
__device__ float g_h   [(size_t)E_MAX * H];
__device__ float g_xkj [(size_t)E_MAX * H];
__device__ float g_wt  [(size_t)9 * H * H];      // 9 transposed+rounded weights [n][k]
__device__ float g_bw  [(size_t)H * NB * H];     // tf32-rounded, k-permuted bil_W copy

// ---------------- helpers ----------------
__device__ __forceinline__ float tf32r(float x) {
    float y; asm("cvt.rna.tf32.f32 %0, %1;" : "=f"(y) : "f"(x)); return y;
}
__device__ __forceinline__ float silu_f(float v) {
    return v * (1.0f / (1.0f + __expf(-v)));
}
__device__ __forceinline__ uint32_t smem_u32(const void* p) {
    uint32_t a;
    asm("{ .reg .u64 t; cvta.to.shared.u64 t, %1; cvt.u32.u64 %0, t; }" : "=r"(a) : "l"(p));
    return a;
}
__device__ __forceinline__ void mma_tf32(float* c, const uint32_t* a, const uint32_t* b) {
    asm volatile(
        "mma.sync.aligned.m16n8k8.row.col.f32.tf32.tf32.f32 "
        "{%0,%1,%2,%3}, {%4,%5,%6,%7}, {%8,%9}, {%0,%1,%2,%3};"
        : "+f"(c[0]), "+f"(c[1]), "+f"(c[2]), "+f"(c[3])
        : "r"(a[0]), "r"(a[1]), "r"(a[2]), "r"(a[3]), "r"(b[0]), "r"(b[1]));
}

#define BP 132      // chain-kernel pitch (132 % 32 == 4, conflict-free LDS.32 frags)
#define BP2 136     // triplet pitch (136 % 32 == 8, conflict-free LDS.64 frags)
#define TILE_B (128 * BP * 4)   // 67584 bytes
#define CP_WAIT() asm volatile("cp.async.wait_group 0;" ::: "memory")

// ---------------- shared GEMM building blocks (512 thr, warps 4m x 4n) ----------
__device__ __forceinline__ void acc_zero(float acc[2][4][4]) {
#pragma unroll
    for (int i = 0; i < 2; i++)
#pragma unroll
        for (int j = 0; j < 4; j++)
#pragma unroll
            for (int e = 0; e < 4; e++) acc[i][j][e] = 0.f;
}

// acc += At @ Bs^T  (operands pre-rounded RNA in SMEM)
__device__ __forceinline__ void mma_128(const float* __restrict__ At,
                                        const float* __restrict__ Bs,
                                        float acc[2][4][4],
                                        int r0, int ncol, int g, int t4)
{
#pragma unroll
    for (int ks = 0; ks < 16; ks++) {
        const int k0 = ks * 8;
        uint32_t a[2][4], bb[4][2];
        a[0][0] = __float_as_uint(At[(r0)      * BP + k0 + t4]);
        a[0][1] = __float_as_uint(At[(r0 + 8)  * BP + k0 + t4]);
        a[0][2] = __float_as_uint(At[(r0)      * BP + k0 + t4 + 4]);
        a[0][3] = __float_as_uint(At[(r0 + 8)  * BP + k0 + t4 + 4]);
        a[1][0] = __float_as_uint(At[(r0 + 16) * BP + k0 + t4]);
        a[1][1] = __float_as_uint(At[(r0 + 24) * BP + k0 + t4]);
        a[1][2] = __float_as_uint(At[(r0 + 16) * BP + k0 + t4 + 4]);
        a[1][3] = __float_as_uint(At[(r0 + 24) * BP + k0 + t4 + 4]);
#pragma unroll
        for (int j = 0; j < 4; j++) {
            int c0 = ncol + j * 8 + g;
            bb[j][0] = __float_as_uint(Bs[c0 * BP + k0 + t4]);
            bb[j][1] = __float_as_uint(Bs[c0 * BP + k0 + t4 + 4]);
        }
#pragma unroll
        for (int i = 0; i < 2; i++)
#pragma unroll
            for (int j = 0; j < 4; j++)
                mma_tf32(acc[i][j], a[i], bb[j]);
    }
}

// weight staging via cp.async (512 threads)
__device__ __forceinline__ void cpasync_w(uint32_t bs_u32, const float* __restrict__ W, int tid) {
#pragma unroll
    for (int i = 0; i < 8; i++) {
        int idx = i * 512 + tid;
        int r = idx >> 5, c4 = idx & 31;
        uint32_t dst = bs_u32 + (uint32_t)(r * BP + c4 * 4) * 4u;
        asm volatile("cp.async.cg.shared.global [%0], [%1], 16;"
                     :: "r"(dst), "l"(W + (size_t)r * H + c4 * 4));
    }
    asm volatile("cp.async.commit_group;" ::: "memory");
}

// stage global tile + RNA-round to tf32
__device__ __forceinline__ void stage_tile_r(float* Tt, const float* __restrict__ A,
                                             int rowBase, int M, int tid) {
#pragma unroll
    for (int i = 0; i < 8; i++) {
        int idx = i * 512 + tid;
        int r = idx >> 5, c4 = idx & 31;
        int grow = rowBase + r;
        float4 v = (grow < M) ? *(const float4*)&A[(size_t)grow * H + c4 * 4]
                              : make_float4(0.f, 0.f, 0.f, 0.f);
        v.x = tf32r(v.x); v.y = tf32r(v.y); v.z = tf32r(v.z); v.w = tf32r(v.w);
        *(float4*)&Tt[r * BP + c4 * 4] = v;
    }
}
// tile <- round(silu(acc + bias))
__device__ __forceinline__ void epi_to_tile(float* Tt, const float acc[2][4][4],
                                            const float* biasS,
                                            int mrow, int ncol, int g, int t4)
{
#pragma unroll
    for (int i = 0; i < 2; i++)
#pragma unroll
        for (int half = 0; half < 2; half++) {
            int row = mrow + i * 16 + half * 8 + g;
#pragma unroll
            for (int j = 0; j < 4; j++) {
                int col = ncol + j * 8 + t4 * 2;
                float v0 = tf32r(silu_f(acc[i][j][half * 2 + 0] + biasS[col]));
                float v1 = tf32r(silu_f(acc[i][j][half * 2 + 1] + biasS[col + 1]));
                *(float2*)&Tt[row * BP + col] = make_float2(v0, v1);
            }
        }
}
// tile <- round(tileR + silu(acc + bias))
__device__ __forceinline__ void epi_res_tile(float* Tt, const float* Tr,
                                             const float acc[2][4][4],
                                             const float* biasS,
                                             int mrow, int ncol, int g, int t4)
{
#pragma unroll
    for (int i = 0; i < 2; i++)
#pragma unroll
        for (int half = 0; half < 2; half++) {
            int row = mrow + i * 16 + half * 8 + g;
#pragma unroll
            for (int j = 0; j < 4; j++) {
                int col = ncol + j * 8 + t4 * 2;
                float2 res = *(float2*)&Tr[row * BP + col];
                float v0 = tf32r(res.x + silu_f(acc[i][j][half * 2 + 0] + biasS[col]));
                float v1 = tf32r(res.y + silu_f(acc[i][j][half * 2 + 1] + biasS[col + 1]));
                *(float2*)&Tt[row * BP + col] = make_float2(v0, v1);
            }
        }
}

// ================= fused x_ji / x_kj / rbf_h kernel ==============================
#define FJ_T0   0
#define FJ_BS   TILE_B
#define FJ_RB   (2 * TILE_B)
#define FJ_BIAS (3 * TILE_B)
#define FJ_SMEM (FJ_BIAS + 1024)
#define RP 20

__global__ void __launch_bounds__(512, 1)
fused_jikj(const float* __restrict__ x, const float* __restrict__ rbf,
           const float* __restrict__ rbfW,
           const float* __restrict__ kjWt, const float* __restrict__ kjb,
           const float* __restrict__ jiWt, const float* __restrict__ jib,
           float* __restrict__ xkj_out, float* __restrict__ h_out, int M)
{
    extern __shared__ char smem[];
    float* T0 = (float*)(smem + FJ_T0);
    float* Bs = (float*)(smem + FJ_BS);
    float* RB = (float*)(smem + FJ_RB);
    float* bKj = (float*)(smem + FJ_BIAS);
    float* bJi = (float*)(smem + FJ_BIAS + 512);
    float* rtile = Bs;
    float* rw    = Bs + 128 * RP;
    const int tid = threadIdx.x;
    const int wid = tid >> 5, lane = tid & 31;
    const int g = lane >> 2, t4 = lane & 3;
    const int rowBase = blockIdx.x * 128;
    const int mrow = (wid & 3) * 32;
    const int ncol = (wid >> 2) * 32;
    const int r0 = mrow + g;
    const uint32_t bs_u32 = smem_u32(Bs);

    stage_tile_r(T0, x, rowBase, M, tid);
    {
        int r = tid >> 2, c4 = tid & 3;
        int grow = rowBase + r;
        float4 v = (grow < M) ? *(const float4*)&rbf[(size_t)grow * NR + c4 * 4]
                              : make_float4(0.f, 0.f, 0.f, 0.f);
        v.x = tf32r(v.x); v.y = tf32r(v.y); v.z = tf32r(v.z); v.w = tf32r(v.w);
        *(float4*)&rtile[r * RP + c4 * 4] = v;
    }
    {
        int n = tid >> 2, k0 = (tid & 3) * 4;
#pragma unroll
        for (int e = 0; e < 4; e++)
            rw[n * RP + k0 + e] = tf32r(rbfW[(size_t)(k0 + e) * H + n]);
    }
    if (tid < 32)       *(float4*)&bKj[tid * 4] = *(const float4*)&kjb[tid * 4];
    else if (tid < 64)  *(float4*)&bJi[(tid - 32) * 4] = *(const float4*)&jib[(tid - 32) * 4];
    __syncthreads();

    // rbf_h tile = rbf @ rbf_W  (K=16)
    float acc[2][4][4];
    acc_zero(acc);
#pragma unroll
    for (int ks = 0; ks < 2; ks++) {
        const int k0 = ks * 8;
        uint32_t a[2][4], bb[4][2];
        a[0][0] = __float_as_uint(rtile[(r0)      * RP + k0 + t4]);
        a[0][1] = __float_as_uint(rtile[(r0 + 8)  * RP + k0 + t4]);
        a[0][2] = __float_as_uint(rtile[(r0)      * RP + k0 + t4 + 4]);
        a[0][3] = __float_as_uint(rtile[(r0 + 8)  * RP + k0 + t4 + 4]);
        a[1][0] = __float_as_uint(rtile[(r0 + 16) * RP + k0 + t4]);
        a[1][1] = __float_as_uint(rtile[(r0 + 24) * RP + k0 + t4]);
        a[1][2] = __float_as_uint(rtile[(r0 + 16) * RP + k0 + t4 + 4]);
        a[1][3] = __float_as_uint(rtile[(r0 + 24) * RP + k0 + t4 + 4]);
#pragma unroll
        for (int j = 0; j < 4; j++) {
            int c0 = ncol + j * 8 + g;
            bb[j][0] = __float_as_uint(rw[c0 * RP + k0 + t4]);
            bb[j][1] = __float_as_uint(rw[c0 * RP + k0 + t4 + 4]);
        }
#pragma unroll
        for (int i = 0; i < 2; i++)
#pragma unroll
            for (int j = 0; j < 4; j++)
                mma_tf32(acc[i][j], a[i], bb[j]);
    }
    __syncthreads();   // rtile/rw reads done -> Bs region free

    cpasync_w(bs_u32, kjWt, tid);      // stream kj weight while writing RB
#pragma unroll
    for (int i = 0; i < 2; i++)
#pragma unroll
        for (int half = 0; half < 2; half++) {
            int row = mrow + i * 16 + half * 8 + g;
#pragma unroll
            for (int j = 0; j < 4; j++) {
                int col = ncol + j * 8 + t4 * 2;
                *(float2*)&RB[row * BP + col] =
                    make_float2(acc[i][j][half * 2], acc[i][j][half * 2 + 1]);
            }
        }
    CP_WAIT();
    __syncthreads();

    // x_kj = silu(silu(x@kjW+b)) * rbf_h
    acc_zero(acc);
    mma_128(T0, Bs, acc, r0, ncol, g, t4);
    __syncthreads();                   // all warps done reading Bs
    cpasync_w(bs_u32, jiWt, tid);      // stream ji weight during kj epilogue
#pragma unroll
    for (int i = 0; i < 2; i++)
#pragma unroll
        for (int half = 0; half < 2; half++) {
            int row = mrow + i * 16 + half * 8 + g;
            int grow = rowBase + row;
            if (grow >= M) continue;
#pragma unroll
            for (int j = 0; j < 4; j++) {
                int col = ncol + j * 8 + t4 * 2;
                float v0 = silu_f(silu_f(acc[i][j][half * 2 + 0] + bKj[col]));
                float v1 = silu_f(silu_f(acc[i][j][half * 2 + 1] + bKj[col + 1]));
                float2 m = *(float2*)&RB[row * BP + col];
                *(float2*)&xkj_out[(size_t)grow * H + col] = make_float2(v0 * m.x, v1 * m.y);
            }
        }
    CP_WAIT();
    __syncthreads();

    // x_ji = silu(silu(x@jiW+b))
    acc_zero(acc);
    mma_128(T0, Bs, acc, r0, ncol, g, t4);
#pragma unroll
    for (int i = 0; i < 2; i++)
#pragma unroll
        for (int half = 0; half < 2; half++) {
            int row = mrow + i * 16 + half * 8 + g;
            int grow = rowBase + row;
            if (grow >= M) continue;
#pragma unroll
            for (int j = 0; j < 4; j++) {
                int col = ncol + j * 8 + t4 * 2;
                float v0 = silu_f(silu_f(acc[i][j][half * 2 + 0] + bJi[col]));
                float v1 = silu_f(silu_f(acc[i][j][half * 2 + 1] + bJi[col + 1]));
                *(float2*)&h_out[(size_t)grow * H + col] = make_float2(v0, v1);
            }
        }
}

// ================= fused chain: pre(3) + post(4) = 7 GEMMs =======================
#define FC_T0   0
#define FC_T1   TILE_B
#define FC_BS   (2 * TILE_B)
#define FC_BIAS (3 * TILE_B)
#define FC_SMEM (FC_BIAS + 7 * 512)

__global__ void __launch_bounds__(512, 1)
fused_chain(const float* __restrict__ h, const float* __restrict__ x,
            const float* __restrict__ Wt,     // 7 weights at Wt + w*H*H (pre1..3, post1..4)
            const float* __restrict__ b1, const float* __restrict__ b2,
            const float* __restrict__ b3, const float* __restrict__ b4,
            const float* __restrict__ b5, const float* __restrict__ b6,
            const float* __restrict__ b7,
            float* __restrict__ outg, int M)
{
    extern __shared__ char smem[];
    float* T0 = (float*)(smem + FC_T0);
    float* T1 = (float*)(smem + FC_T1);
    float* Bs = (float*)(smem + FC_BS);
    float* bS = (float*)(smem + FC_BIAS);    // [7][128]
    const int tid = threadIdx.x;
    const int wid = tid >> 5, lane = tid & 31;
    const int g = lane >> 2, t4 = lane & 3;
    const int rowBase = blockIdx.x * 128;
    const int mrow = (wid & 3) * 32;
    const int ncol = (wid >> 2) * 32;
    const int r0 = mrow + g;
    const uint32_t bs_u32 = smem_u32(Bs);

    cpasync_w(bs_u32, Wt, tid);              // W1 streams during staging
    stage_tile_r(T0, h, rowBase, M, tid);
    if (tid < 224) {
        int w = tid >> 5, c = (tid & 31) * 4;
        const float* bp = (w == 0) ? b1 : (w == 1) ? b2 : (w == 2) ? b3 :
                          (w == 3) ? b4 : (w == 4) ? b5 : (w == 5) ? b6 : b7;
        *(float4*)&bS[w * 128 + c] = *(const float4*)&bp[c];
    }
    CP_WAIT();
    __syncthreads();

    float acc[2][4][4];

    // 1: u = silu(h@W1+b1) -> T1
    acc_zero(acc);
    mma_128(T0, Bs, acc, r0, ncol, g, t4);
    __syncthreads();
    cpasync_w(bs_u32, Wt + 1 * H * H, tid);
    epi_to_tile(T1, acc, bS + 0 * 128, mrow, ncol, g, t4);
    CP_WAIT();
    __syncthreads();

    // 2: v = h + silu(u@W2+b2) -> T1
    acc_zero(acc);
    mma_128(T1, Bs, acc, r0, ncol, g, t4);
    __syncthreads();
    cpasync_w(bs_u32, Wt + 2 * H * H, tid);
    epi_res_tile(T1, T0, acc, bS + 1 * 128, mrow, ncol, g, t4);
    CP_WAIT();
    __syncthreads();

    // 3: out0 = round(silu(v@W3+b3) + x) -> T0
    acc_zero(acc);
    mma_128(T1, Bs, acc, r0, ncol, g, t4);
    __syncthreads();
    cpasync_w(bs_u32, Wt + 3 * H * H, tid);
#pragma unroll
    for (int i = 0; i < 2; i++)
#pragma unroll
        for (int half = 0; half < 2; half++) {
            int row = mrow + i * 16 + half * 8 + g;
            int grow = rowBase + row;
#pragma unroll
            for (int j = 0; j < 4; j++) {
                int col = ncol + j * 8 + t4 * 2;
                float2 xv = (grow < M) ? *(const float2*)&x[(size_t)grow * H + col]
                                       : make_float2(0.f, 0.f);
                float v0 = tf32r(silu_f(acc[i][j][half * 2 + 0] + bS[2 * 128 + col]) + xv.x);
                float v1 = tf32r(silu_f(acc[i][j][half * 2 + 1] + bS[2 * 128 + col + 1]) + xv.y);
                *(float2*)&T0[row * BP + col] = make_float2(v0, v1);
            }
        }
    CP_WAIT();
    __syncthreads();

    // 4: u2 = silu(out0@W4+b4) -> T1
    acc_zero(acc);
    mma_128(T0, Bs, acc, r0, ncol, g, t4);
    __syncthreads();
    cpasync_w(bs_u32, Wt + 4 * H * H, tid);
    epi_to_tile(T1, acc, bS + 3 * 128, mrow, ncol, g, t4);
    CP_WAIT();
    __syncthreads();

    // 5: out1 = out0 + silu(u2@W5+b5) -> T0
    acc_zero(acc);
    mma_128(T1, Bs, acc, r0, ncol, g, t4);
    __syncthreads();
    cpasync_w(bs_u32, Wt + 5 * H * H, tid);
    epi_res_tile(T0, T0, acc, bS + 4 * 128, mrow, ncol, g, t4);
    CP_WAIT();
    __syncthreads();

    // 6: u3 = silu(out1@W6+b6) -> T1
    acc_zero(acc);
    mma_128(T0, Bs, acc, r0, ncol, g, t4);
    __syncthreads();
    cpasync_w(bs_u32, Wt + 6 * H * H, tid);
    epi_to_tile(T1, acc, bS + 5 * 128, mrow, ncol, g, t4);
    CP_WAIT();
    __syncthreads();

    // 7: out = out1 + silu(u3@W7+b7) -> global (full precision)
    acc_zero(acc);
    mma_128(T1, Bs, acc, r0, ncol, g, t4);
#pragma unroll
    for (int i = 0; i < 2; i++)
#pragma unroll
        for (int half = 0; half < 2; half++) {
            int row = mrow + i * 16 + half * 8 + g;
            int grow = rowBase + row;
            if (grow >= M) continue;
#pragma unroll
            for (int j = 0; j < 4; j++) {
                int col = ncol + j * 8 + t4 * 2;
                float2 res = *(float2*)&T0[row * BP + col];
                float v0 = res.x + silu_f(acc[i][j][half * 2 + 0] + bS[6 * 128 + col]);
                float v1 = res.y + silu_f(acc[i][j][half * 2 + 1] + bS[6 * 128 + col + 1]);
                *(float2*)&outg[(size_t)grow * H + col] = make_float2(v0, v1);
            }
        }
}

// ================= fused triplet (byte-identical to R14) =========================
#define TR2J   0
#define TR2K   256
#define TR2S   512
#define TR2W   2560
#define TR2RAW 6144
#define TR2B   (TR2RAW + 64 * BP2 * 4)
#define TR2_SMEM (TR2B + 128 * BP2 * 4)
#define SP 113

__device__ __forceinline__ void cpasync_bw2(uint32_t bs_u32, const float* __restrict__ bw,
                                            int b, int tid)
{
#pragma unroll
    for (int i = 0; i < 16; i++) {
        int c = i * 256 + tid;
        int r = c >> 5, c4 = c & 31;
        uint32_t dst = bs_u32 + (uint32_t)(r * BP2 + c4 * 4) * 4u;
        const float* src = bw + (size_t)r * (NB * H) + b * H + c4 * 4;
        asm volatile("cp.async.cg.shared.global [%0], [%1], 16;" :: "r"(dst), "l"(src));
    }
    asm volatile("cp.async.commit_group;" ::: "memory");
}

__global__ void __launch_bounds__(256, 2)
triplet_fused(const float* __restrict__ xkj,
              const float* __restrict__ sbf, const float* __restrict__ sbfW,
              const int* __restrict__ kj, const int* __restrict__ ji,
              const float* __restrict__ bw, float* __restrict__ hout, int T)
{
    extern __shared__ char smem[];
    int* ji_s = (int*)(smem + TR2J);
    int* ek_s = (int*)(smem + TR2K);
    float* sbf_s = (float*)(smem + TR2S);
    float* ws_s = (float*)(smem + TR2W);
    float* raw = (float*)(smem + TR2RAW);
    float* Bs = (float*)(smem + TR2B);
    float* stile = Bs;
    const int tid = threadIdx.x;
    const int wid = tid >> 5, lane = tid & 31;
    const int g = lane >> 2, t4 = lane & 3;
    const int tBase = blockIdx.x * 64;
    const int mrow = (wid & 1) * 32;
    const int ncol = (wid >> 1) * 32;
    const int r0 = mrow + g;
    const uint32_t bs_u32 = smem_u32(Bs);

    if (tid < 64) {
        int t = tBase + tid;
        ji_s[tid] = (t < T) ? ji[t] : 0;
        ek_s[tid] = (t < T) ? kj[t] : 0;
    }
    if (tid < 224) *(float4*)&ws_s[tid * 4] = *(const float4*)&sbfW[tid * 4];
#pragma unroll
    for (int i = 0; i < 7; i++) {
        int idx = i * 256 + tid;
        int r = idx / 28, c = idx % 28;
        int t = tBase + r;
        float4 v = (t < T) ? *(const float4*)&sbf[(size_t)t * NSR + c * 4]
                           : make_float4(0.f, 0.f, 0.f, 0.f);
        stile[r * SP + c * 4 + 0] = v.x;
        stile[r * SP + c * 4 + 1] = v.y;
        stile[r * SP + c * 4 + 2] = v.z;
        stile[r * SP + c * 4 + 3] = v.w;
    }
    __syncthreads();

    {
        const int r = tid >> 2, q = tid & 3;
        float a8[NB];
#pragma unroll
        for (int o = 0; o < NB; o++) a8[o] = 0.f;
        const float* myrow = &stile[r * SP + q * 28];
        const float* myw = &ws_s[q * 28 * NB];
#pragma unroll 4
        for (int k = 0; k < 28; k++) {
            float s = myrow[k];
            float4 w0 = *(const float4*)&myw[k * NB];
            float4 w1 = *(const float4*)&myw[k * NB + 4];
            a8[0] = fmaf(s, w0.x, a8[0]); a8[1] = fmaf(s, w0.y, a8[1]);
            a8[2] = fmaf(s, w0.z, a8[2]); a8[3] = fmaf(s, w0.w, a8[3]);
            a8[4] = fmaf(s, w1.x, a8[4]); a8[5] = fmaf(s, w1.y, a8[5]);
            a8[6] = fmaf(s, w1.z, a8[6]); a8[7] = fmaf(s, w1.w, a8[7]);
        }
#pragma unroll
        for (int o = 0; o < NB; o++) {
            a8[o] += __shfl_xor_sync(0xffffffffu, a8[o], 1);
            a8[o] += __shfl_xor_sync(0xffffffffu, a8[o], 2);
        }
        if (q == 0) {
            *(float4*)&sbf_s[r * NB]     = make_float4(a8[0], a8[1], a8[2], a8[3]);
            *(float4*)&sbf_s[r * NB + 4] = make_float4(a8[4], a8[5], a8[6], a8[7]);
        }
    }
#pragma unroll
    for (int i = 0; i < 4; i++) {
        int idx = i * 256 + tid;
        int r = idx >> 4, grp = idx & 15;
        int e = ek_s[r];
        const float* src = &xkj[(size_t)e * H + grp * 8];
        float4 lo = *(const float4*)src;
        float4 hi = *(const float4*)(src + 4);
        float2* dst = (float2*)&raw[r * BP2 + grp * 8];
        dst[0] = make_float2(lo.x, hi.x);
        dst[1] = make_float2(lo.y, hi.y);
        dst[2] = make_float2(lo.z, hi.z);
        dst[3] = make_float2(lo.w, hi.w);
    }

    float acc[2][4][4];
    acc_zero(acc);

    for (int b = 0; b < NB; b++) {
        __syncthreads();
        cpasync_bw2(bs_u32, bw, b, tid);
        CP_WAIT();
        __syncthreads();

        const float s0 = sbf_s[(r0)      * NB + b];
        const float s1 = sbf_s[(r0 + 8)  * NB + b];
        const float s2 = sbf_s[(r0 + 16) * NB + b];
        const float s3 = sbf_s[(r0 + 24) * NB + b];

#pragma unroll
        for (int ks = 0; ks < 16; ks++) {
            const int k0 = ks * 8;
            uint32_t a[2][4], bb[4][2];
            float2 v00 = *(float2*)&raw[(r0)      * BP2 + k0 + 2 * t4];
            float2 v01 = *(float2*)&raw[(r0 + 8)  * BP2 + k0 + 2 * t4];
            float2 v10 = *(float2*)&raw[(r0 + 16) * BP2 + k0 + 2 * t4];
            float2 v11 = *(float2*)&raw[(r0 + 24) * BP2 + k0 + 2 * t4];
            a[0][0] = __float_as_uint(v00.x * s0); a[0][2] = __float_as_uint(v00.y * s0);
            a[0][1] = __float_as_uint(v01.x * s1); a[0][3] = __float_as_uint(v01.y * s1);
            a[1][0] = __float_as_uint(v10.x * s2); a[1][2] = __float_as_uint(v10.y * s2);
            a[1][1] = __float_as_uint(v11.x * s3); a[1][3] = __float_as_uint(v11.y * s3);
#pragma unroll
            for (int j = 0; j < 4; j++) {
                int c0 = ncol + j * 8 + g;
                float2 w = *(float2*)&Bs[c0 * BP2 + k0 + 2 * t4];
                bb[j][0] = __float_as_uint(w.x);
                bb[j][1] = __float_as_uint(w.y);
            }
#pragma unroll
            for (int i = 0; i < 2; i++)
#pragma unroll
                for (int j = 0; j < 4; j++)
                    mma_tf32(acc[i][j], a[i], bb[j]);
        }
    }

#pragma unroll
    for (int i = 0; i < 2; i++) {
#pragma unroll
        for (int half = 0; half < 2; half++) {
            int r = mrow + i * 16 + half * 8 + g;
            int t = tBase + r;
            if (t >= T) continue;
            float* dst = &hout[(size_t)ji_s[r] * H];
#pragma unroll
            for (int j = 0; j < 4; j++) {
                int col = ncol + j * 8 + t4 * 2;
                atomicAdd(dst + col,     acc[i][j][half * 2 + 0]);
                atomicAdd(dst + col + 1, acc[i][j][half * 2 + 1]);
            }
        }
    }
}

// ================= weight prep ===================================================
struct W9 { const float* p[9]; };
__global__ void transpose_w(W9 ws, float* __restrict__ out)
{
    int w = blockIdx.y;
    const float* in = ws.p[w];
    float* o = out + (size_t)w * H * H;
    int idx = blockIdx.x * 256 + threadIdx.x;
    int n = idx >> 7, k = idx & 127;
    o[n * H + k] = tf32r(in[k * H + n]);
}
__global__ void round_bilw(const float* __restrict__ in, float* __restrict__ out)
{
    int idx = blockIdx.x * 256 + threadIdx.x;
    if (idx >= H * NB * H) return;
    int k = idx & 127;
    int base = idx - k;
    int p = (k & ~7) + 2 * (k & 3) + ((k >> 2) & 1);
    out[base + p] = tf32r(in[idx]);
}

// ================= launch ========================================================
extern "C" void kernel_launch(void* const* d_in, const int* in_sizes, int n_in,
                              void* d_out, int out_size)
{
    const float* x      = (const float*)d_in[0];
    const float* rbf    = (const float*)d_in[1];
    const float* sbf    = (const float*)d_in[2];
    const int*   kj     = (const int*)  d_in[3];
    const int*   ji     = (const int*)  d_in[4];
    const float* rbf_W  = (const float*)d_in[5];
    const float* sbf_W  = (const float*)d_in[6];
    const float* ji_W   = (const float*)d_in[7];
    const float* ji_b   = (const float*)d_in[8];
    const float* kj_W   = (const float*)d_in[9];
    const float* kj_b   = (const float*)d_in[10];
    const float* bil_W  = (const float*)d_in[11];
    const float* pre_b1 = (const float*)d_in[13];
    const float* pre_b2 = (const float*)d_in[15];
    const float* pre_b3 = (const float*)d_in[17];
    const float* post_b1 = (const float*)d_in[19];
    const float* post_b2 = (const float*)d_in[21];
    const float* post_b3 = (const float*)d_in[23];
    const float* post_b4 = (const float*)d_in[25];
    float* out = (float*)d_out;

    const int E = in_sizes[0] / H;
    const int T = in_sizes[3];

    float *p_h, *p_xkj, *p_wt, *p_bw;
    cudaGetSymbolAddress((void**)&p_h,    g_h);
    cudaGetSymbolAddress((void**)&p_xkj,  g_xkj);
    cudaGetSymbolAddress((void**)&p_wt,   g_wt);
    cudaGetSymbolAddress((void**)&p_bw,   g_bw);

    cudaFuncSetAttribute(fused_jikj,  cudaFuncAttributeMaxDynamicSharedMemorySize, FJ_SMEM);
    cudaFuncSetAttribute(fused_chain, cudaFuncAttributeMaxDynamicSharedMemorySize, FC_SMEM);
    cudaFuncSetAttribute(triplet_fused, cudaFuncAttributeMaxDynamicSharedMemorySize, TR2_SMEM);

    const int gE = (E + 127) / 128;
    const int gT = (T + 63) / 64;

    // 0. weight prep: g_wt[0]=jiW, [1]=kjW, [2..8]=pre1..3,post1..4 (chain order)
    W9 ws;
    ws.p[0] = ji_W; ws.p[1] = kj_W;
    ws.p[2] = (const float*)d_in[12]; ws.p[3] = (const float*)d_in[14]; ws.p[4] = (const float*)d_in[16];
    ws.p[5] = (const float*)d_in[18]; ws.p[6] = (const float*)d_in[20];
    ws.p[7] = (const float*)d_in[22]; ws.p[8] = (const float*)d_in[24];
    transpose_w<<<dim3(64, 9), 256>>>(ws, p_wt);
    round_bilw<<<(H * NB * H + 255) / 256, 256>>>(bil_W, p_bw);

    // 1. x_kj -> g_xkj, x_ji -> g_h (+ in-smem rbf_h)
    fused_jikj<<<gE, 512, FJ_SMEM>>>(x, rbf, rbf_W,
                                     p_wt + 1 * H * H, kj_b,
                                     p_wt + 0 * H * H, ji_b,
                                     p_xkj, p_h, E);
    // 2. triplet: sbf_h in-kernel + bilinear + scatter-add into g_h
    triplet_fused<<<gT, 256, TR2_SMEM>>>(p_xkj, sbf, sbf_W, kj, ji, p_bw, p_h, T);
    // 3. full MLP chain (7 GEMMs fused): g_h -> out
    fused_chain<<<gE, 512, FC_SMEM>>>(p_h, x, p_wt + 2 * H * H,
                                      pre_b1, pre_b2, pre_b3,
                                      post_b1, post_b2, post_b3, post_b4,
                                      out, E);
}

// round 17
// speedup vs baseline: 1.1815x; 1.0916x over previous
#include <cuda_runtime.h>
#include <cuda_fp16.h>
#include <cstdint>

// ---------------- problem constants ----------------
#define E_MAX 100000
#define T_MAX 200000
#define H 128
#define NR 16
#define NSR 112
#define NB 8

// ---------------- scratch ----------------
__device__ float  g_h   [(size_t)E_MAX * H];
__device__ float  g_xkj [(size_t)E_MAX * H];
__device__ float  g_wt  [(size_t)9 * H * H];     // 9 transposed+rounded weights [n][k]
__device__ __half g_bwh [(size_t)H * NB * H];    // fp16, slot-permuted bil_W

// ---------------- helpers ----------------
__device__ __forceinline__ float tf32r(float x) {
    float y; asm("cvt.rna.tf32.f32 %0, %1;" : "=f"(y) : "f"(x)); return y;
}
__device__ __forceinline__ float silu_f(float v) {
    return v * (1.0f / (1.0f + __expf(-v)));
}
__device__ __forceinline__ uint32_t smem_u32(const void* p) {
    uint32_t a;
    asm("{ .reg .u64 t; cvta.to.shared.u64 t, %1; cvt.u32.u64 %0, t; }" : "=r"(a) : "l"(p));
    return a;
}
__device__ __forceinline__ void mma_tf32(float* c, const uint32_t* a, const uint32_t* b) {
    asm volatile(
        "mma.sync.aligned.m16n8k8.row.col.f32.tf32.tf32.f32 "
        "{%0,%1,%2,%3}, {%4,%5,%6,%7}, {%8,%9}, {%0,%1,%2,%3};"
        : "+f"(c[0]), "+f"(c[1]), "+f"(c[2]), "+f"(c[3])
        : "r"(a[0]), "r"(a[1]), "r"(a[2]), "r"(a[3]), "r"(b[0]), "r"(b[1]));
}
__device__ __forceinline__ void mma_f16(float* c, const uint32_t* a, const uint32_t* b) {
    asm volatile(
        "mma.sync.aligned.m16n8k16.row.col.f32.f16.f16.f32 "
        "{%0,%1,%2,%3}, {%4,%5,%6,%7}, {%8,%9}, {%0,%1,%2,%3};"
        : "+f"(c[0]), "+f"(c[1]), "+f"(c[2]), "+f"(c[3])
        : "r"(a[0]), "r"(a[1]), "r"(a[2]), "r"(a[3]), "r"(b[0]), "r"(b[1]));
}
// pack two f32 -> f16x2 (hi goes to upper 16 bits)
__device__ __forceinline__ uint32_t packh2(float hi, float lo) {
    uint32_t d;
    asm("cvt.rn.f16x2.f32 %0, %1, %2;" : "=r"(d) : "f"(hi), "f"(lo));
    return d;
}

#define BP 132      // chain pitch (conflict-free LDS.32 frags)
#define TRP 136     // triplet raw fp32 pitch (136 % 32 == 8 -> LDS.64 ok)
#define TH 144      // triplet B fp16 pitch in halves (288 B/row, bank-safe)
#define TILE_B (128 * BP * 4)
#define CP_WAIT() asm volatile("cp.async.wait_group 0;" ::: "memory")

// ---------------- shared GEMM building blocks (512 thr, warps 4m x 4n) ----------
__device__ __forceinline__ void acc_zero(float acc[2][4][4]) {
#pragma unroll
    for (int i = 0; i < 2; i++)
#pragma unroll
        for (int j = 0; j < 4; j++)
#pragma unroll
            for (int e = 0; e < 4; e++) acc[i][j][e] = 0.f;
}

__device__ __forceinline__ void mma_128(const float* __restrict__ At,
                                        const float* __restrict__ Bs,
                                        float acc[2][4][4],
                                        int r0, int ncol, int g, int t4)
{
#pragma unroll
    for (int ks = 0; ks < 16; ks++) {
        const int k0 = ks * 8;
        uint32_t a[2][4], bb[4][2];
        a[0][0] = __float_as_uint(At[(r0)      * BP + k0 + t4]);
        a[0][1] = __float_as_uint(At[(r0 + 8)  * BP + k0 + t4]);
        a[0][2] = __float_as_uint(At[(r0)      * BP + k0 + t4 + 4]);
        a[0][3] = __float_as_uint(At[(r0 + 8)  * BP + k0 + t4 + 4]);
        a[1][0] = __float_as_uint(At[(r0 + 16) * BP + k0 + t4]);
        a[1][1] = __float_as_uint(At[(r0 + 24) * BP + k0 + t4]);
        a[1][2] = __float_as_uint(At[(r0 + 16) * BP + k0 + t4 + 4]);
        a[1][3] = __float_as_uint(At[(r0 + 24) * BP + k0 + t4 + 4]);
#pragma unroll
        for (int j = 0; j < 4; j++) {
            int c0 = ncol + j * 8 + g;
            bb[j][0] = __float_as_uint(Bs[c0 * BP + k0 + t4]);
            bb[j][1] = __float_as_uint(Bs[c0 * BP + k0 + t4 + 4]);
        }
#pragma unroll
        for (int i = 0; i < 2; i++)
#pragma unroll
            for (int j = 0; j < 4; j++)
                mma_tf32(acc[i][j], a[i], bb[j]);
    }
}

__device__ __forceinline__ void cpasync_w(uint32_t bs_u32, const float* __restrict__ W, int tid) {
#pragma unroll
    for (int i = 0; i < 8; i++) {
        int idx = i * 512 + tid;
        int r = idx >> 5, c4 = idx & 31;
        uint32_t dst = bs_u32 + (uint32_t)(r * BP + c4 * 4) * 4u;
        asm volatile("cp.async.cg.shared.global [%0], [%1], 16;"
                     :: "r"(dst), "l"(W + (size_t)r * H + c4 * 4));
    }
    asm volatile("cp.async.commit_group;" ::: "memory");
}

__device__ __forceinline__ void stage_tile_r(float* Tt, const float* __restrict__ A,
                                             int rowBase, int M, int tid) {
#pragma unroll
    for (int i = 0; i < 8; i++) {
        int idx = i * 512 + tid;
        int r = idx >> 5, c4 = idx & 31;
        int grow = rowBase + r;
        float4 v = (grow < M) ? *(const float4*)&A[(size_t)grow * H + c4 * 4]
                              : make_float4(0.f, 0.f, 0.f, 0.f);
        v.x = tf32r(v.x); v.y = tf32r(v.y); v.z = tf32r(v.z); v.w = tf32r(v.w);
        *(float4*)&Tt[r * BP + c4 * 4] = v;
    }
}
__device__ __forceinline__ void epi_to_tile(float* Tt, const float acc[2][4][4],
                                            const float* biasS,
                                            int mrow, int ncol, int g, int t4)
{
#pragma unroll
    for (int i = 0; i < 2; i++)
#pragma unroll
        for (int half = 0; half < 2; half++) {
            int row = mrow + i * 16 + half * 8 + g;
#pragma unroll
            for (int j = 0; j < 4; j++) {
                int col = ncol + j * 8 + t4 * 2;
                float v0 = tf32r(silu_f(acc[i][j][half * 2 + 0] + biasS[col]));
                float v1 = tf32r(silu_f(acc[i][j][half * 2 + 1] + biasS[col + 1]));
                *(float2*)&Tt[row * BP + col] = make_float2(v0, v1);
            }
        }
}
__device__ __forceinline__ void epi_res_tile(float* Tt, const float* Tr,
                                             const float acc[2][4][4],
                                             const float* biasS,
                                             int mrow, int ncol, int g, int t4)
{
#pragma unroll
    for (int i = 0; i < 2; i++)
#pragma unroll
        for (int half = 0; half < 2; half++) {
            int row = mrow + i * 16 + half * 8 + g;
#pragma unroll
            for (int j = 0; j < 4; j++) {
                int col = ncol + j * 8 + t4 * 2;
                float2 res = *(float2*)&Tr[row * BP + col];
                float v0 = tf32r(res.x + silu_f(acc[i][j][half * 2 + 0] + biasS[col]));
                float v1 = tf32r(res.y + silu_f(acc[i][j][half * 2 + 1] + biasS[col + 1]));
                *(float2*)&Tt[row * BP + col] = make_float2(v0, v1);
            }
        }
}

// ================= fused x_ji / x_kj / rbf_h kernel (R16-identical) ==============
#define FJ_T0   0
#define FJ_BS   TILE_B
#define FJ_RB   (2 * TILE_B)
#define FJ_BIAS (3 * TILE_B)
#define FJ_SMEM (FJ_BIAS + 1024)
#define RP 20

__global__ void __launch_bounds__(512, 1)
fused_jikj(const float* __restrict__ x, const float* __restrict__ rbf,
           const float* __restrict__ rbfW,
           const float* __restrict__ kjWt, const float* __restrict__ kjb,
           const float* __restrict__ jiWt, const float* __restrict__ jib,
           float* __restrict__ xkj_out, float* __restrict__ h_out, int M)
{
    extern __shared__ char smem[];
    float* T0 = (float*)(smem + FJ_T0);
    float* Bs = (float*)(smem + FJ_BS);
    float* RB = (float*)(smem + FJ_RB);
    float* bKj = (float*)(smem + FJ_BIAS);
    float* bJi = (float*)(smem + FJ_BIAS + 512);
    float* rtile = Bs;
    float* rw    = Bs + 128 * RP;
    const int tid = threadIdx.x;
    const int wid = tid >> 5, lane = tid & 31;
    const int g = lane >> 2, t4 = lane & 3;
    const int rowBase = blockIdx.x * 128;
    const int mrow = (wid & 3) * 32;
    const int ncol = (wid >> 2) * 32;
    const int r0 = mrow + g;
    const uint32_t bs_u32 = smem_u32(Bs);

    stage_tile_r(T0, x, rowBase, M, tid);
    {
        int r = tid >> 2, c4 = tid & 3;
        int grow = rowBase + r;
        float4 v = (grow < M) ? *(const float4*)&rbf[(size_t)grow * NR + c4 * 4]
                              : make_float4(0.f, 0.f, 0.f, 0.f);
        v.x = tf32r(v.x); v.y = tf32r(v.y); v.z = tf32r(v.z); v.w = tf32r(v.w);
        *(float4*)&rtile[r * RP + c4 * 4] = v;
    }
    {
        int n = tid >> 2, k0 = (tid & 3) * 4;
#pragma unroll
        for (int e = 0; e < 4; e++)
            rw[n * RP + k0 + e] = tf32r(rbfW[(size_t)(k0 + e) * H + n]);
    }
    if (tid < 32)       *(float4*)&bKj[tid * 4] = *(const float4*)&kjb[tid * 4];
    else if (tid < 64)  *(float4*)&bJi[(tid - 32) * 4] = *(const float4*)&jib[(tid - 32) * 4];
    __syncthreads();

    float acc[2][4][4];
    acc_zero(acc);
#pragma unroll
    for (int ks = 0; ks < 2; ks++) {
        const int k0 = ks * 8;
        uint32_t a[2][4], bb[4][2];
        a[0][0] = __float_as_uint(rtile[(r0)      * RP + k0 + t4]);
        a[0][1] = __float_as_uint(rtile[(r0 + 8)  * RP + k0 + t4]);
        a[0][2] = __float_as_uint(rtile[(r0)      * RP + k0 + t4 + 4]);
        a[0][3] = __float_as_uint(rtile[(r0 + 8)  * RP + k0 + t4 + 4]);
        a[1][0] = __float_as_uint(rtile[(r0 + 16) * RP + k0 + t4]);
        a[1][1] = __float_as_uint(rtile[(r0 + 24) * RP + k0 + t4]);
        a[1][2] = __float_as_uint(rtile[(r0 + 16) * RP + k0 + t4 + 4]);
        a[1][3] = __float_as_uint(rtile[(r0 + 24) * RP + k0 + t4 + 4]);
#pragma unroll
        for (int j = 0; j < 4; j++) {
            int c0 = ncol + j * 8 + g;
            bb[j][0] = __float_as_uint(rw[c0 * RP + k0 + t4]);
            bb[j][1] = __float_as_uint(rw[c0 * RP + k0 + t4 + 4]);
        }
#pragma unroll
        for (int i = 0; i < 2; i++)
#pragma unroll
            for (int j = 0; j < 4; j++)
                mma_tf32(acc[i][j], a[i], bb[j]);
    }
    __syncthreads();

    cpasync_w(bs_u32, kjWt, tid);
#pragma unroll
    for (int i = 0; i < 2; i++)
#pragma unroll
        for (int half = 0; half < 2; half++) {
            int row = mrow + i * 16 + half * 8 + g;
#pragma unroll
            for (int j = 0; j < 4; j++) {
                int col = ncol + j * 8 + t4 * 2;
                *(float2*)&RB[row * BP + col] =
                    make_float2(acc[i][j][half * 2], acc[i][j][half * 2 + 1]);
            }
        }
    CP_WAIT();
    __syncthreads();

    acc_zero(acc);
    mma_128(T0, Bs, acc, r0, ncol, g, t4);
    __syncthreads();
    cpasync_w(bs_u32, jiWt, tid);
#pragma unroll
    for (int i = 0; i < 2; i++)
#pragma unroll
        for (int half = 0; half < 2; half++) {
            int row = mrow + i * 16 + half * 8 + g;
            int grow = rowBase + row;
            if (grow >= M) continue;
#pragma unroll
            for (int j = 0; j < 4; j++) {
                int col = ncol + j * 8 + t4 * 2;
                float v0 = silu_f(silu_f(acc[i][j][half * 2 + 0] + bKj[col]));
                float v1 = silu_f(silu_f(acc[i][j][half * 2 + 1] + bKj[col + 1]));
                float2 m = *(float2*)&RB[row * BP + col];
                *(float2*)&xkj_out[(size_t)grow * H + col] = make_float2(v0 * m.x, v1 * m.y);
            }
        }
    CP_WAIT();
    __syncthreads();

    acc_zero(acc);
    mma_128(T0, Bs, acc, r0, ncol, g, t4);
#pragma unroll
    for (int i = 0; i < 2; i++)
#pragma unroll
        for (int half = 0; half < 2; half++) {
            int row = mrow + i * 16 + half * 8 + g;
            int grow = rowBase + row;
            if (grow >= M) continue;
#pragma unroll
            for (int j = 0; j < 4; j++) {
                int col = ncol + j * 8 + t4 * 2;
                float v0 = silu_f(silu_f(acc[i][j][half * 2 + 0] + bJi[col]));
                float v1 = silu_f(silu_f(acc[i][j][half * 2 + 1] + bJi[col + 1]));
                *(float2*)&h_out[(size_t)grow * H + col] = make_float2(v0, v1);
            }
        }
}

// ================= fused chain: 7 GEMMs (R16-identical) ==========================
#define FC_T0   0
#define FC_T1   TILE_B
#define FC_BS   (2 * TILE_B)
#define FC_BIAS (3 * TILE_B)
#define FC_SMEM (FC_BIAS + 7 * 512)

__global__ void __launch_bounds__(512, 1)
fused_chain(const float* __restrict__ h, const float* __restrict__ x,
            const float* __restrict__ Wt,
            const float* __restrict__ b1, const float* __restrict__ b2,
            const float* __restrict__ b3, const float* __restrict__ b4,
            const float* __restrict__ b5, const float* __restrict__ b6,
            const float* __restrict__ b7,
            float* __restrict__ outg, int M)
{
    extern __shared__ char smem[];
    float* T0 = (float*)(smem + FC_T0);
    float* T1 = (float*)(smem + FC_T1);
    float* Bs = (float*)(smem + FC_BS);
    float* bS = (float*)(smem + FC_BIAS);
    const int tid = threadIdx.x;
    const int wid = tid >> 5, lane = tid & 31;
    const int g = lane >> 2, t4 = lane & 3;
    const int rowBase = blockIdx.x * 128;
    const int mrow = (wid & 3) * 32;
    const int ncol = (wid >> 2) * 32;
    const int r0 = mrow + g;
    const uint32_t bs_u32 = smem_u32(Bs);

    cpasync_w(bs_u32, Wt, tid);
    stage_tile_r(T0, h, rowBase, M, tid);
    if (tid < 224) {
        int w = tid >> 5, c = (tid & 31) * 4;
        const float* bp = (w == 0) ? b1 : (w == 1) ? b2 : (w == 2) ? b3 :
                          (w == 3) ? b4 : (w == 4) ? b5 : (w == 5) ? b6 : b7;
        *(float4*)&bS[w * 128 + c] = *(const float4*)&bp[c];
    }
    CP_WAIT();
    __syncthreads();

    float acc[2][4][4];

    acc_zero(acc);
    mma_128(T0, Bs, acc, r0, ncol, g, t4);
    __syncthreads();
    cpasync_w(bs_u32, Wt + 1 * H * H, tid);
    epi_to_tile(T1, acc, bS + 0 * 128, mrow, ncol, g, t4);
    CP_WAIT();
    __syncthreads();

    acc_zero(acc);
    mma_128(T1, Bs, acc, r0, ncol, g, t4);
    __syncthreads();
    cpasync_w(bs_u32, Wt + 2 * H * H, tid);
    epi_res_tile(T1, T0, acc, bS + 1 * 128, mrow, ncol, g, t4);
    CP_WAIT();
    __syncthreads();

    acc_zero(acc);
    mma_128(T1, Bs, acc, r0, ncol, g, t4);
    __syncthreads();
    cpasync_w(bs_u32, Wt + 3 * H * H, tid);
#pragma unroll
    for (int i = 0; i < 2; i++)
#pragma unroll
        for (int half = 0; half < 2; half++) {
            int row = mrow + i * 16 + half * 8 + g;
            int grow = rowBase + row;
#pragma unroll
            for (int j = 0; j < 4; j++) {
                int col = ncol + j * 8 + t4 * 2;
                float2 xv = (grow < M) ? *(const float2*)&x[(size_t)grow * H + col]
                                       : make_float2(0.f, 0.f);
                float v0 = tf32r(silu_f(acc[i][j][half * 2 + 0] + bS[2 * 128 + col]) + xv.x);
                float v1 = tf32r(silu_f(acc[i][j][half * 2 + 1] + bS[2 * 128 + col + 1]) + xv.y);
                *(float2*)&T0[row * BP + col] = make_float2(v0, v1);
            }
        }
    CP_WAIT();
    __syncthreads();

    acc_zero(acc);
    mma_128(T0, Bs, acc, r0, ncol, g, t4);
    __syncthreads();
    cpasync_w(bs_u32, Wt + 4 * H * H, tid);
    epi_to_tile(T1, acc, bS + 3 * 128, mrow, ncol, g, t4);
    CP_WAIT();
    __syncthreads();

    acc_zero(acc);
    mma_128(T1, Bs, acc, r0, ncol, g, t4);
    __syncthreads();
    cpasync_w(bs_u32, Wt + 5 * H * H, tid);
    epi_res_tile(T0, T0, acc, bS + 4 * 128, mrow, ncol, g, t4);
    CP_WAIT();
    __syncthreads();

    acc_zero(acc);
    mma_128(T0, Bs, acc, r0, ncol, g, t4);
    __syncthreads();
    cpasync_w(bs_u32, Wt + 6 * H * H, tid);
    epi_to_tile(T1, acc, bS + 5 * 128, mrow, ncol, g, t4);
    CP_WAIT();
    __syncthreads();

    acc_zero(acc);
    mma_128(T1, Bs, acc, r0, ncol, g, t4);
#pragma unroll
    for (int i = 0; i < 2; i++)
#pragma unroll
        for (int half = 0; half < 2; half++) {
            int row = mrow + i * 16 + half * 8 + g;
            int grow = rowBase + row;
            if (grow >= M) continue;
#pragma unroll
            for (int j = 0; j < 4; j++) {
                int col = ncol + j * 8 + t4 * 2;
                float2 res = *(float2*)&T0[row * BP + col];
                float v0 = res.x + silu_f(acc[i][j][half * 2 + 0] + bS[6 * 128 + col]);
                float v1 = res.y + silu_f(acc[i][j][half * 2 + 1] + bS[6 * 128 + col + 1]);
                *(float2*)&outg[(size_t)grow * H + col] = make_float2(v0, v1);
            }
        }
}

// ================= fused triplet: fp16 m16n8k16 mainloop =========================
// 64 triplets x 128 cols, 256 threads, 8 warps (2m x 4n), warp tile 32x32.
#define TRJ   0
#define TRK   256
#define TRS   512                        // sbf_s [64][8]   2 KB
#define TRW   2560                       // ws_s  [112][8]  3.5 KB
#define TRRAW 6144                       // raw [64][TRP] fp32  34816 B
#define TRB   (TRRAW + 64 * TRP * 4)     // Bsh [128][TH] fp16  36864 B
#define TR_SMEM (TRB + 128 * TH * 2)     // 77824 B -> 2 CTAs/SM
#define SP 113

// stage one fp16 bilW channel into Bsh via cp.async (256 threads, 2048 x 16B)
__device__ __forceinline__ void cpasync_bwh(uint32_t bs_u32, const __half* __restrict__ bwh,
                                            int b, int tid)
{
#pragma unroll
    for (int i = 0; i < 8; i++) {
        int c = i * 256 + tid;           // 0..2047 chunks of 16B (8 halves)
        int o = c >> 4, c16 = c & 15;
        uint32_t dst = bs_u32 + (uint32_t)(o * TH + c16 * 8) * 2u;
        const __half* src = bwh + ((size_t)o * NB + b) * 128 + c16 * 8;
        asm volatile("cp.async.ca.shared.global [%0], [%1], 16;" :: "r"(dst), "l"(src));
    }
    asm volatile("cp.async.commit_group;" ::: "memory");
}

__global__ void __launch_bounds__(256, 2)
triplet_fused(const float* __restrict__ xkj,
              const float* __restrict__ sbf, const float* __restrict__ sbfW,
              const int* __restrict__ kj, const int* __restrict__ ji,
              const __half* __restrict__ bwh, float* __restrict__ hout, int T)
{
    extern __shared__ char smem[];
    int* ji_s = (int*)(smem + TRJ);
    int* ek_s = (int*)(smem + TRK);
    float* sbf_s = (float*)(smem + TRS);
    float* ws_s = (float*)(smem + TRW);
    float* raw = (float*)(smem + TRRAW);
    __half* Bsh = (__half*)(smem + TRB);
    float* stile = (float*)Bsh;          // [64][SP] sbf staging (28.9KB <= 36.9KB)
    const int tid = threadIdx.x;
    const int wid = tid >> 5, lane = tid & 31;
    const int g = lane >> 2, t4 = lane & 3;
    const int tBase = blockIdx.x * 64;
    const int mrow = (wid & 1) * 32;
    const int ncol = (wid >> 1) * 32;
    const int r0 = mrow + g;
    const uint32_t bs_u32 = smem_u32(Bsh);

    if (tid < 64) {
        int t = tBase + tid;
        ji_s[tid] = (t < T) ? ji[t] : 0;
        ek_s[tid] = (t < T) ? kj[t] : 0;
    }
    if (tid < 224) *(float4*)&ws_s[tid * 4] = *(const float4*)&sbfW[tid * 4];
#pragma unroll
    for (int i = 0; i < 7; i++) {
        int idx = i * 256 + tid;
        int r = idx / 28, c = idx % 28;
        int t = tBase + r;
        float4 v = (t < T) ? *(const float4*)&sbf[(size_t)t * NSR + c * 4]
                           : make_float4(0.f, 0.f, 0.f, 0.f);
        stile[r * SP + c * 4 + 0] = v.x;
        stile[r * SP + c * 4 + 1] = v.y;
        stile[r * SP + c * 4 + 2] = v.z;
        stile[r * SP + c * 4 + 3] = v.w;
    }
    __syncthreads();

    // sbf_h: 4 threads per row, 28 k's each, shfl-reduce
    {
        const int r = tid >> 2, q = tid & 3;
        float a8[NB];
#pragma unroll
        for (int o = 0; o < NB; o++) a8[o] = 0.f;
        const float* myrow = &stile[r * SP + q * 28];
        const float* myw = &ws_s[q * 28 * NB];
#pragma unroll 4
        for (int k = 0; k < 28; k++) {
            float s = myrow[k];
            float4 w0 = *(const float4*)&myw[k * NB];
            float4 w1 = *(const float4*)&myw[k * NB + 4];
            a8[0] = fmaf(s, w0.x, a8[0]); a8[1] = fmaf(s, w0.y, a8[1]);
            a8[2] = fmaf(s, w0.z, a8[2]); a8[3] = fmaf(s, w0.w, a8[3]);
            a8[4] = fmaf(s, w1.x, a8[4]); a8[5] = fmaf(s, w1.y, a8[5]);
            a8[6] = fmaf(s, w1.z, a8[6]); a8[7] = fmaf(s, w1.w, a8[7]);
        }
#pragma unroll
        for (int o = 0; o < NB; o++) {
            a8[o] += __shfl_xor_sync(0xffffffffu, a8[o], 1);
            a8[o] += __shfl_xor_sync(0xffffffffu, a8[o], 2);
        }
        if (q == 0) {
            *(float4*)&sbf_s[r * NB]     = make_float4(a8[0], a8[1], a8[2], a8[3]);
            *(float4*)&sbf_s[r * NB + 4] = make_float4(a8[4], a8[5], a8[6], a8[7]);
        }
    }
    // gather x_kj rows into raw (plain fp32 layout)
#pragma unroll
    for (int i = 0; i < 8; i++) {
        int idx = i * 256 + tid;
        int r = idx >> 5, c4 = idx & 31;
        int e = ek_s[r];
        *(float4*)&raw[r * TRP + c4 * 4] = *(const float4*)&xkj[(size_t)e * H + c4 * 4];
    }

    float acc[2][4][4];
    acc_zero(acc);

    for (int b = 0; b < NB; b++) {
        __syncthreads();                 // prev mma Bsh reads done (1st iter: stile done)
        cpasync_bwh(bs_u32, bwh, b, tid);
        CP_WAIT();
        __syncthreads();

        const float s0 = sbf_s[(r0)      * NB + b];
        const float s1 = sbf_s[(r0 + 8)  * NB + b];
        const float s2 = sbf_s[(r0 + 16) * NB + b];
        const float s3 = sbf_s[(r0 + 24) * NB + b];

#pragma unroll
        for (int kg = 0; kg < 8; kg++) {
            const int kf = kg * 16;
            uint32_t a[2][4], bb[4][2];
            // A: rows r0(+8,+16,+24); k pairs (kf+2t4, +1) and (kf+8+2t4, +1)
            {
                float2 p0 = *(float2*)&raw[(r0)      * TRP + kf + 2 * t4];
                float2 q0 = *(float2*)&raw[(r0)      * TRP + kf + 8 + 2 * t4];
                a[0][0] = packh2(p0.y * s0, p0.x * s0);
                a[0][2] = packh2(q0.y * s0, q0.x * s0);
                float2 p1 = *(float2*)&raw[(r0 + 8)  * TRP + kf + 2 * t4];
                float2 q1 = *(float2*)&raw[(r0 + 8)  * TRP + kf + 8 + 2 * t4];
                a[0][1] = packh2(p1.y * s1, p1.x * s1);
                a[0][3] = packh2(q1.y * s1, q1.x * s1);
                float2 p2 = *(float2*)&raw[(r0 + 16) * TRP + kf + 2 * t4];
                float2 q2 = *(float2*)&raw[(r0 + 16) * TRP + kf + 8 + 2 * t4];
                a[1][0] = packh2(p2.y * s2, p2.x * s2);
                a[1][2] = packh2(q2.y * s2, q2.x * s2);
                float2 p3 = *(float2*)&raw[(r0 + 24) * TRP + kf + 2 * t4];
                float2 q3 = *(float2*)&raw[(r0 + 24) * TRP + kf + 8 + 2 * t4];
                a[1][1] = packh2(p3.y * s3, p3.x * s3);
                a[1][3] = packh2(q3.y * s3, q3.x * s3);
            }
            // B: one LDS.64 per n-subtile (slot-permuted fp16 weights)
#pragma unroll
            for (int j = 0; j < 4; j++) {
                int o = ncol + j * 8 + g;
                uint2 w = *(uint2*)&Bsh[o * TH + kg * 16 + 4 * t4];
                bb[j][0] = w.x;
                bb[j][1] = w.y;
            }
#pragma unroll
            for (int i = 0; i < 2; i++)
#pragma unroll
                for (int j = 0; j < 4; j++)
                    mma_f16(acc[i][j], a[i], bb[j]);
        }
    }

    // scatter-add epilogue
#pragma unroll
    for (int i = 0; i < 2; i++) {
#pragma unroll
        for (int half = 0; half < 2; half++) {
            int r = mrow + i * 16 + half * 8 + g;
            int t = tBase + r;
            if (t >= T) continue;
            float* dst = &hout[(size_t)ji_s[r] * H];
#pragma unroll
            for (int j = 0; j < 4; j++) {
                int col = ncol + j * 8 + t4 * 2;
                atomicAdd(dst + col,     acc[i][j][half * 2 + 0]);
                atomicAdd(dst + col + 1, acc[i][j][half * 2 + 1]);
            }
        }
    }
}

// ================= weight prep ===================================================
struct W9 { const float* p[9]; };
__global__ void transpose_w(W9 ws, float* __restrict__ out)
{
    int w = blockIdx.y;
    const float* in = ws.p[w];
    float* o = out + (size_t)w * H * H;
    int idx = blockIdx.x * 256 + threadIdx.x;
    int n = idx >> 7, k = idx & 127;
    o[n * H + k] = tf32r(in[k * H + n]);
}
// fp16 + slot-permute bil_W: slot(kk) = 4*((kk&7)>>1) + 2*(kk>>3) + (kk&1)
__global__ void conv_bilw(const float* __restrict__ in, __half* __restrict__ out)
{
    int idx = blockIdx.x * 256 + threadIdx.x;
    if (idx >= H * NB * H) return;
    int k = idx & 127;
    int kk = k & 15;
    int slot = 4 * ((kk & 7) >> 1) + 2 * (kk >> 3) + (kk & 1);
    int p = (k & ~15) + slot;
    out[(idx - k) + p] = __float2half_rn(in[idx]);
}

// ================= launch ========================================================
extern "C" void kernel_launch(void* const* d_in, const int* in_sizes, int n_in,
                              void* d_out, int out_size)
{
    const float* x      = (const float*)d_in[0];
    const float* rbf    = (const float*)d_in[1];
    const float* sbf    = (const float*)d_in[2];
    const int*   kj     = (const int*)  d_in[3];
    const int*   ji     = (const int*)  d_in[4];
    const float* rbf_W  = (const float*)d_in[5];
    const float* sbf_W  = (const float*)d_in[6];
    const float* ji_W   = (const float*)d_in[7];
    const float* ji_b   = (const float*)d_in[8];
    const float* kj_W   = (const float*)d_in[9];
    const float* kj_b   = (const float*)d_in[10];
    const float* bil_W  = (const float*)d_in[11];
    const float* pre_b1 = (const float*)d_in[13];
    const float* pre_b2 = (const float*)d_in[15];
    const float* pre_b3 = (const float*)d_in[17];
    const float* post_b1 = (const float*)d_in[19];
    const float* post_b2 = (const float*)d_in[21];
    const float* post_b3 = (const float*)d_in[23];
    const float* post_b4 = (const float*)d_in[25];
    float* out = (float*)d_out;

    const int E = in_sizes[0] / H;
    const int T = in_sizes[3];

    float *p_h, *p_xkj, *p_wt;
    __half* p_bwh;
    cudaGetSymbolAddress((void**)&p_h,    g_h);
    cudaGetSymbolAddress((void**)&p_xkj,  g_xkj);
    cudaGetSymbolAddress((void**)&p_wt,   g_wt);
    cudaGetSymbolAddress((void**)&p_bwh,  g_bwh);

    cudaFuncSetAttribute(fused_jikj,  cudaFuncAttributeMaxDynamicSharedMemorySize, FJ_SMEM);
    cudaFuncSetAttribute(fused_chain, cudaFuncAttributeMaxDynamicSharedMemorySize, FC_SMEM);
    cudaFuncSetAttribute(triplet_fused, cudaFuncAttributeMaxDynamicSharedMemorySize, TR_SMEM);

    const int gE = (E + 127) / 128;
    const int gT = (T + 63) / 64;

    // 0. weight prep
    W9 ws;
    ws.p[0] = ji_W; ws.p[1] = kj_W;
    ws.p[2] = (const float*)d_in[12]; ws.p[3] = (const float*)d_in[14]; ws.p[4] = (const float*)d_in[16];
    ws.p[5] = (const float*)d_in[18]; ws.p[6] = (const float*)d_in[20];
    ws.p[7] = (const float*)d_in[22]; ws.p[8] = (const float*)d_in[24];
    transpose_w<<<dim3(64, 9), 256>>>(ws, p_wt);
    conv_bilw<<<(H * NB * H + 255) / 256, 256>>>(bil_W, p_bwh);

    // 1. x_kj -> g_xkj, x_ji -> g_h (+ in-smem rbf_h)
    fused_jikj<<<gE, 512, FJ_SMEM>>>(x, rbf, rbf_W,
                                     p_wt + 1 * H * H, kj_b,
                                     p_wt + 0 * H * H, ji_b,
                                     p_xkj, p_h, E);
    // 2. triplet: sbf_h in-kernel + fp16 bilinear + scatter-add into g_h
    triplet_fused<<<gT, 256, TR_SMEM>>>(p_xkj, sbf, sbf_W, kj, ji, p_bwh, p_h, T);
    // 3. full MLP chain (7 GEMMs fused): g_h -> out
    fused_chain<<<gE, 512, FC_SMEM>>>(p_h, x, p_wt + 2 * H * H,
                                      pre_b1, pre_b2, pre_b3,
                                      post_b1, post_b2, post_b3, post_b4,
                                      out, E);
}